// round 8
// baseline (speedup 1.0000x reference)
#include <cuda_runtime.h>
#include <cstdint>

#define T_    256
#define N_    4096
#define C_    12
#define D_    256
#define K_    12
#define KPAD  136          // 272/2 k-pairs: 128 h + 6 x/onehot + 2 pad
#define KPP   (KPAD + 2)   // padded for prefetch over-read
#define RB    32
#define NTHR  256
#define NBLK  (N_ / RB)    // 128

typedef unsigned long long ull;

// ---- smem layout (ull units) ----
#define U_SH   0                       // h_aug [(KPAD+2)][32] ull
#define U_WY   (U_SH + KPP * RB)       // Wy paired [12][128] ull
#define U_BE   (U_WY + 12 * 128)       // enc bias {b,0} [256]
#define U_BD   (U_BE + 256)            // dec bias {b,0} [256]
#define U_YT   (U_BD + 256)            // ytmp 384 floats = 192 ull
#define U_BY   (U_YT + 192)            // by 12 floats (pad 16)
#define U_TOT  (U_BY + 8)
#define SMEM_BYTES (U_TOT * 8)         // ~53 KB

// W pre-paired: g_Wp[phase][kp][d] = {W(d,2kp), W(d,2kp+1)}; kp>=128 -> Wx cols; kp>=134 -> 0
// 2 pad kp rows per phase so depth-2 prefetch can over-read safely.
__device__ float2 g_Wp[2][KPP][D_];

__device__ __forceinline__ void ffma2(ull &d, ull a, ull b) {
    asm("fma.rn.f32x2 %0, %1, %2, %0;" : "+l"(d) : "l"(a), "l"(b));
}
__device__ __forceinline__ void unpack2(ull v, float &lo, float &hi) {
    asm("mov.b64 {%0, %1}, %2;" : "=f"(lo), "=f"(hi) : "l"(v));
}
__device__ __forceinline__ ull pk(float a, float b) {
    ull r; asm("mov.b64 %0, {%1, %2};" : "=l"(r) : "f"(a), "f"(b)); return r;
}
__device__ __forceinline__ float shflx(float v, int m) {
    float r;
    asm("shfl.sync.bfly.b32 %0, %1, %2, 0x1f, 0xffffffff;" : "=f"(r) : "f"(v), "r"(m));
    return r;
}
// one h value (duplicated pair) times 8 outputs
__device__ __forceinline__ void row8(ull* a, ull h,
                                     const ulonglong2 &w0, const ulonglong2 &w1,
                                     const ulonglong2 &w2, const ulonglong2 &w3) {
    ffma2(a[0], h, w0.x); ffma2(a[1], h, w0.y);
    ffma2(a[2], h, w1.x); ffma2(a[3], h, w1.y);
    ffma2(a[4], h, w2.x); ffma2(a[5], h, w2.y);
    ffma2(a[6], h, w3.x); ffma2(a[7], h, w3.y);
}

// ---------------- prep: paired fused weight image ----------------
__global__ void prep_kernel(const float* __restrict__ eWh, const float* __restrict__ eWx,
                            const float* __restrict__ dWh, const float* __restrict__ dWx)
{
    int p  = blockIdx.x / KPP;
    int kp = blockIdx.x % KPP;
    int d  = threadIdx.x;
    const float* Wh = p ? dWh : eWh;
    const float* Wx = p ? dWx : eWx;
    int k0 = 2 * kp, k1 = 2 * kp + 1;
    float v0 = (k0 < D_) ? Wh[d * D_ + k0] : ((k0 < D_ + C_) ? Wx[d * C_ + (k0 - D_)] : 0.f);
    float v1 = (k1 < D_) ? Wh[d * D_ + k1] : ((k1 < D_ + C_) ? Wx[d * C_ + (k1 - D_)] : 0.f);
    g_Wp[p][kp][d] = make_float2(v0, v1);   // pad rows (kp>=134) become 0
}

// ---------------- main persistent kernel ----------------
extern "C" __global__ void __launch_bounds__(NTHR, 1)
seq2seq_kernel(const float* __restrict__ x,
               const float* __restrict__ ebx, const float* __restrict__ dbx,
               const float* __restrict__ dWy, const float* __restrict__ dby,
               float* __restrict__ out)
{
    extern __shared__ ull smu[];
    ull*   sh  = smu + U_SH;
    ull*   sWy = smu + U_WY;
    ull*   sbe = smu + U_BE;
    ull*   sbd = smu + U_BD;
    float* yt  = (float*)(smu + U_YT);
    float* sby = (float*)(smu + U_BY);

    const int tid  = threadIdx.x;
    const int lane = tid & 31;
    const int warp = tid >> 5;
    const int r0   = (tid & 7) * 4;       // 4 rows
    const int d0   = (tid >> 3) * 8;      // 8 outputs (ull index == output index)
    const int rowbase = blockIdx.x * RB;

    const int c1 = tid >> 5;              // aug staging (tid<192): pair-col, row
    const int r1 = tid & 31;

    // ---- init ----
    for (int i = tid; i < KPP * RB; i += NTHR) sh[i] = 0ull;
    for (int i = tid; i < 12 * 128; i += NTHR) sWy[i] = ((const ull*)dWy)[i];
    for (int i = tid; i < D_; i += NTHR) {
        sbe[i] = pk(ebx[i], 0.f);
        sbd[i] = pk(dbx[i], 0.f);
    }
    if (tid < K_) sby[tid] = dby[tid];
    __syncthreads();

    // stage x_0 into aug rows (192 slots)
    if (tid < 192) {
        const float2 a = *(const float2*)(x + ((size_t)rowbase + r1) * C_ + 2 * c1);
        sh[(128 + c1) * RB + r1] = pk(a.x, a.y);
    }
    __syncthreads();

    // per-thread W pointers (ulonglong2 units); kp stride = D_/2 = 128
    const ulonglong2* const wbase0 =
        (const ulonglong2*)&g_Wp[0][0][0] + (d0 >> 1);
    const ulonglong2* const wbase1 =
        (const ulonglong2*)&g_Wp[1][0][0] + (d0 >> 1);

    ull acc[32];

    for (int t = 0; t < 2 * T_; ++t) {
        const bool dec = (t >= T_);

        // prefetch next x slice into regs (encoder)
        ull xv = 0ull;
        if (!dec && (t + 1) < T_ && tid < 192) {
            const float2 a = *(const float2*)(x + ((size_t)(t + 1) * N_ + rowbase + r1) * C_ + 2 * c1);
            xv = pk(a.x, a.y);
        }

        // acc init = {bias, 0}
        {
            const ulonglong2* bp = (const ulonglong2*)((dec ? sbd : sbe) + d0);
            ulonglong2 b01 = bp[0], b23 = bp[1], b45 = bp[2], b67 = bp[3];
            ull bj[8] = {b01.x, b01.y, b23.x, b23.y, b45.x, b45.y, b67.x, b67.y};
            #pragma unroll
            for (int i = 0; i < 4; ++i)
                #pragma unroll
                for (int j = 0; j < 8; ++j) acc[i * 8 + j] = bj[j];
        }

        // ---- GEMM: flat kp loop; W from L2 via depth-2 LDG prefetch ----
        {
            const ulonglong2* wq = dec ? wbase1 : wbase0;
            const ulonglong2* hq = (const ulonglong2*)(sh + r0);

            // prime: W for kp0 (A), kp1 (B); h for kp0
            ulonglong2 wa0 = wq[0], wa1 = wq[1], wa2 = wq[2], wa3 = wq[3]; wq += 128;
            ulonglong2 wb0 = wq[0], wb1 = wq[1], wb2 = wq[2], wb3 = wq[3]; wq += 128;
            ulonglong2 ha0 = hq[0], ha1 = hq[1]; hq += 16;

            #pragma unroll 2
            for (int kp = 0; kp < KPAD; kp += 2) {
                // h for kp+1
                ulonglong2 hb0 = hq[0], hb1 = hq[1]; hq += 16;

                // compute kp (A regs)
                row8(acc + 0,  ha0.x, wa0, wa1, wa2, wa3);
                row8(acc + 8,  ha0.y, wa0, wa1, wa2, wa3);
                row8(acc + 16, ha1.x, wa0, wa1, wa2, wa3);
                row8(acc + 24, ha1.y, wa0, wa1, wa2, wa3);

                // prefetch kp+2 (W into A regs, h) — pad rows make over-read safe
                wa0 = wq[0]; wa1 = wq[1]; wa2 = wq[2]; wa3 = wq[3]; wq += 128;
                ha0 = hq[0]; ha1 = hq[1]; hq += 16;

                // compute kp+1 (B regs)
                row8(acc + 0,  hb0.x, wb0, wb1, wb2, wb3);
                row8(acc + 8,  hb0.y, wb0, wb1, wb2, wb3);
                row8(acc + 16, hb1.x, wb0, wb1, wb2, wb3);
                row8(acc + 24, hb1.y, wb0, wb1, wb2, wb3);

                // prefetch kp+3 (W into B regs)
                wb0 = wq[0]; wb1 = wq[1]; wb2 = wq[2]; wb3 = wq[3]; wq += 128;
            }
            // note: hq over-read covered by sh pad rows 136..137 (zeroed)
        }

        __syncthreads();   // S1: all reads of old h/aug done

        // ---- epilogue: h = relu(lo+hi), store paired h ----
        #pragma unroll
        for (int j2 = 0; j2 < 4; ++j2) {
            float4* dst = (float4*)(sh + ((d0 >> 1) + j2) * RB + r0);
            #pragma unroll
            for (int i2 = 0; i2 < 2; ++i2) {
                float a0, b0, a1, b1, a2, b2, a3, b3;
                unpack2(acc[(2 * i2) * 8 + 2 * j2],         a0, b0);
                unpack2(acc[(2 * i2) * 8 + 2 * j2 + 1],     a1, b1);
                unpack2(acc[(2 * i2 + 1) * 8 + 2 * j2],     a2, b2);
                unpack2(acc[(2 * i2 + 1) * 8 + 2 * j2 + 1], a3, b3);
                dst[i2] = make_float4(fmaxf(a0 + b0, 0.f), fmaxf(a1 + b1, 0.f),
                                      fmaxf(a2 + b2, 0.f), fmaxf(a3 + b3, 0.f));
            }
        }
        if (tid < 192) {
            if (!dec) {   // stage x_{t+1} or SOS (col 10 -> pair 5 = {1,0})
                sh[(128 + c1) * RB + r1] =
                    (t + 1 < T_) ? xv : ((c1 == 5) ? pk(1.f, 0.f) : 0ull);
            } else {      // clear previous one-hot
                sh[(128 + c1) * RB + r1] = 0ull;
            }
        }
        __syncthreads();   // S2: new h (+aug/zero) visible

        // ---- decoder: tiled y = h @ Wy^T + by, argmax, one-hot feedback ----
        if (dec) {
            const int kg = lane & 3;          // k in {kg, kg+4, kg+8}
            const int mg = lane >> 2;         // m-chunk [16*mg, 16*mg+16)
            const ull* hb = sh + 4 * warp;    // rows 4*warp..+3
            const ull* w0 = sWy + kg * 128;
            const ull* w1 = sWy + (kg + 4) * 128;
            const ull* w2 = sWy + (kg + 8) * 128;
            ull a[12];
            #pragma unroll
            for (int q = 0; q < 12; ++q) a[q] = 0ull;
            const int mbase = mg * 16;
            #pragma unroll 4
            for (int mm = 0; mm < 16; ++mm) {
                const int m = mbase + mm;
                const ulonglong2* hp = (const ulonglong2*)(hb + m * RB);
                ulonglong2 hA = hp[0], hB = hp[1];
                ull hr[4] = {hA.x, hA.y, hB.x, hB.y};
                ull wv0 = w0[m], wv1 = w1[m], wv2 = w2[m];
                #pragma unroll
                for (int i = 0; i < 4; ++i) {
                    ffma2(a[i * 3 + 0], hr[i], wv0);
                    ffma2(a[i * 3 + 1], hr[i], wv1);
                    ffma2(a[i * 3 + 2], hr[i], wv2);
                }
            }
            float v[12];
            #pragma unroll
            for (int q = 0; q < 12; ++q) {
                float lo, hi; unpack2(a[q], lo, hi);
                v[q] = lo + hi;
            }
            #pragma unroll
            for (int q = 0; q < 12; ++q) {
                v[q] += shflx(v[q], 4);
                v[q] += shflx(v[q], 8);
                v[q] += shflx(v[q], 16);
            }
            if (mg == 0) {
                #pragma unroll
                for (int i = 0; i < 4; ++i) {
                    yt[(4 * warp + i) * 12 + kg]     = v[i * 3 + 0] + sby[kg];
                    yt[(4 * warp + i) * 12 + kg + 4] = v[i * 3 + 1] + sby[kg + 4];
                    yt[(4 * warp + i) * 12 + kg + 8] = v[i * 3 + 2] + sby[kg + 8];
                }
            }
            __syncthreads();   // yt complete
            if (tid < 32) {
                const float* yr = yt + tid * 12;
                float vv[12];
                #pragma unroll
                for (int q = 0; q < 3; ++q) {
                    float4 fv = *(const float4*)(yr + 4 * q);
                    vv[4 * q] = fv.x; vv[4 * q + 1] = fv.y;
                    vv[4 * q + 2] = fv.z; vv[4 * q + 3] = fv.w;
                }
                float best = vv[0]; int sel = 0;
                #pragma unroll
                for (int q = 1; q < 12; ++q)
                    if (vv[q] > best) { best = vv[q]; sel = q; }   // first-max wins
                float* og = out + ((size_t)(t - T_) * N_ + rowbase + tid) * K_;
                *(float4*)(og)     = make_float4(vv[0], vv[1], vv[2],  vv[3]);
                *(float4*)(og + 4) = make_float4(vv[4], vv[5], vv[6],  vv[7]);
                *(float4*)(og + 8) = make_float4(vv[8], vv[9], vv[10], vv[11]);
                sh[(128 + (sel >> 1)) * RB + tid] = (sel & 1) ? pk(0.f, 1.f) : pk(1.f, 0.f);
            }
            __syncthreads();   // one-hot visible before next step's reads
        }
    }
}

extern "C" void kernel_launch(void* const* d_in, const int* in_sizes, int n_in,
                              void* d_out, int out_size) {
    const float* x   = (const float*)d_in[0];
    const float* eWx = (const float*)d_in[1];
    const float* ebx = (const float*)d_in[2];
    const float* eWh = (const float*)d_in[3];
    const float* dWx = (const float*)d_in[6];
    const float* dbx = (const float*)d_in[7];
    const float* dWh = (const float*)d_in[8];
    const float* dWy = (const float*)d_in[9];
    const float* dby = (const float*)d_in[10];

    prep_kernel<<<2 * KPP, D_>>>(eWh, eWx, dWh, dWx);

    cudaFuncSetAttribute(seq2seq_kernel,
                         cudaFuncAttributeMaxDynamicSharedMemorySize, SMEM_BYTES);
    seq2seq_kernel<<<NBLK, NTHR, SMEM_BYTES>>>(
        x, ebx, dbx, dWy, dby, (float*)d_out);
}

// round 9
// speedup vs baseline: 1.0949x; 1.0949x over previous
#include <cuda_runtime.h>
#include <cstdint>

#define T_    256
#define N_    4096
#define C_    12
#define D_    256
#define K_    12
#define KPAD  136          // 272/2 k-pairs: 128 h + 6 x/onehot + 2 pad
#define KPP   (KPAD + 2)   // padded for prefetch over-read
#define RB    32
#define NTHR  128
#define NBLK  (N_ / RB)    // 128

typedef unsigned long long ull;

// ---- smem layout (ull units) ----
#define U_SH   0                       // h_aug [(KPAD+2)][32] ull
#define U_WY   (U_SH + KPP * RB)       // Wy paired [12][128] ull
#define U_BE   (U_WY + 12 * 128)       // enc bias {b,0} [256]
#define U_BD   (U_BE + 256)            // dec bias {b,0} [256]
#define U_YT   (U_BD + 256)            // ytmp 384 floats = 192 ull
#define U_BY   (U_YT + 192)            // by 12 floats (pad 16)
#define U_TOT  (U_BY + 8)
#define SMEM_BYTES (U_TOT * 8)         // ~53 KB

// W pre-paired: g_Wp[phase][kp][d] = {W(d,2kp), W(d,2kp+1)}; kp>=128 -> Wx cols; kp>=134 -> 0
// 2 pad kp rows per phase so depth-2 prefetch can over-read safely.
__device__ float2 g_Wp[2][KPP][D_];

__device__ __forceinline__ void ffma2(ull &d, ull a, ull b) {
    asm("fma.rn.f32x2 %0, %1, %2, %0;" : "+l"(d) : "l"(a), "l"(b));
}
__device__ __forceinline__ void unpack2(ull v, float &lo, float &hi) {
    asm("mov.b64 {%0, %1}, %2;" : "=f"(lo), "=f"(hi) : "l"(v));
}
__device__ __forceinline__ ull pk(float a, float b) {
    ull r; asm("mov.b64 %0, {%1, %2};" : "=l"(r) : "f"(a), "f"(b)); return r;
}
__device__ __forceinline__ float shflx(float v, int m) {
    float r;
    asm("shfl.sync.bfly.b32 %0, %1, %2, 0x1f, 0xffffffff;" : "=f"(r) : "f"(v), "r"(m));
    return r;
}
// one h value (duplicated k-pair for one row) times 8 outputs
__device__ __forceinline__ void row8(ull* a, ull h,
                                     const ulonglong2 &w0, const ulonglong2 &w1,
                                     const ulonglong2 &w2, const ulonglong2 &w3) {
    ffma2(a[0], h, w0.x); ffma2(a[1], h, w0.y);
    ffma2(a[2], h, w1.x); ffma2(a[3], h, w1.y);
    ffma2(a[4], h, w2.x); ffma2(a[5], h, w2.y);
    ffma2(a[6], h, w3.x); ffma2(a[7], h, w3.y);
}

// ---------------- prep: paired fused weight image ----------------
__global__ void prep_kernel(const float* __restrict__ eWh, const float* __restrict__ eWx,
                            const float* __restrict__ dWh, const float* __restrict__ dWx)
{
    int p  = blockIdx.x / KPP;
    int kp = blockIdx.x % KPP;
    int d  = threadIdx.x;
    const float* Wh = p ? dWh : eWh;
    const float* Wx = p ? dWx : eWx;
    int k0 = 2 * kp, k1 = 2 * kp + 1;
    float v0 = (k0 < D_) ? Wh[d * D_ + k0] : ((k0 < D_ + C_) ? Wx[d * C_ + (k0 - D_)] : 0.f);
    float v1 = (k1 < D_) ? Wh[d * D_ + k1] : ((k1 < D_ + C_) ? Wx[d * C_ + (k1 - D_)] : 0.f);
    g_Wp[p][kp][d] = make_float2(v0, v1);   // pad rows (kp>=134) are 0
}

// ---------------- main persistent kernel ----------------
extern "C" __global__ void __launch_bounds__(NTHR, 1)
seq2seq_kernel(const float* __restrict__ x,
               const float* __restrict__ ebx, const float* __restrict__ dbx,
               const float* __restrict__ dWy, const float* __restrict__ dby,
               float* __restrict__ out)
{
    extern __shared__ ull smu[];
    ull*   sh  = smu + U_SH;
    ull*   sWy = smu + U_WY;
    ull*   sbe = smu + U_BE;
    ull*   sbd = smu + U_BD;
    float* yt  = (float*)(smu + U_YT);
    float* sby = (float*)(smu + U_BY);

    const int tid  = threadIdx.x;
    const int lane = tid & 31;
    const int warp = tid >> 5;
    const int r0   = (tid & 3) * 8;       // 8 rows
    const int d0   = (tid >> 2) * 8;      // 8 outputs (ull index == output index)
    const int rowbase = blockIdx.x * RB;

    const int c1 = tid >> 5;              // aug staging: pair-col (slot tid), row
    const int r1 = tid & 31;

    // ---- init ----
    for (int i = tid; i < KPP * RB; i += NTHR) sh[i] = 0ull;
    for (int i = tid; i < 12 * 128; i += NTHR) sWy[i] = ((const ull*)dWy)[i];
    for (int i = tid; i < D_; i += NTHR) {
        sbe[i] = pk(ebx[i], 0.f);
        sbd[i] = pk(dbx[i], 0.f);
    }
    if (tid < K_) sby[tid] = dby[tid];
    __syncthreads();

    // stage x_0 into aug rows (192 slots: tid, and tid+128 for tid<64)
    {
        const float2 a = *(const float2*)(x + ((size_t)rowbase + r1) * C_ + 2 * c1);
        sh[(128 + c1) * RB + r1] = pk(a.x, a.y);
        if (tid < 64) {
            const float2 b = *(const float2*)(x + ((size_t)rowbase + r1) * C_ + 2 * (4 + c1));
            sh[(132 + c1) * RB + r1] = pk(b.x, b.y);
        }
    }
    __syncthreads();

    // per-thread W pointers (ulonglong2 units); kp stride = D_/2 = 128 ull2
    const ulonglong2* const wbase0 = (const ulonglong2*)&g_Wp[0][0][0] + (d0 >> 1);
    const ulonglong2* const wbase1 = (const ulonglong2*)&g_Wp[1][0][0] + (d0 >> 1);

    ull acc[64];

    for (int t = 0; t < 2 * T_; ++t) {
        const bool dec = (t >= T_);

        // prefetch next x slice into regs (encoder)
        ull xv1 = 0ull, xv2 = 0ull;
        if (!dec && (t + 1) < T_) {
            const float2 a = *(const float2*)(x + ((size_t)(t + 1) * N_ + rowbase + r1) * C_ + 2 * c1);
            xv1 = pk(a.x, a.y);
            if (tid < 64) {
                const float2 b = *(const float2*)(x + ((size_t)(t + 1) * N_ + rowbase + r1) * C_ + 2 * (4 + c1));
                xv2 = pk(b.x, b.y);
            }
        }

        // acc init = {bias, 0}
        {
            const ulonglong2* bp = (const ulonglong2*)((dec ? sbd : sbe) + d0);
            ulonglong2 b01 = bp[0], b23 = bp[1], b45 = bp[2], b67 = bp[3];
            ull bj[8] = {b01.x, b01.y, b23.x, b23.y, b45.x, b45.y, b67.x, b67.y};
            #pragma unroll
            for (int i = 0; i < 8; ++i)
                #pragma unroll
                for (int j = 0; j < 8; ++j) acc[i * 8 + j] = bj[j];
        }

        // ---- GEMM: flat kp loop; W depth-2 LDG prefetch, h depth-1 LDS ----
        {
            const ulonglong2* wq = dec ? wbase1 : wbase0;
            const ulonglong2* hq = (const ulonglong2*)(sh + r0);

            // prime: W for kp0 (A), kp1 (B); h for kp0 (A)
            ulonglong2 wa0 = wq[0], wa1 = wq[1], wa2 = wq[2], wa3 = wq[3]; wq += 128;
            ulonglong2 wb0 = wq[0], wb1 = wq[1], wb2 = wq[2], wb3 = wq[3]; wq += 128;
            ulonglong2 ha0 = hq[0], ha1 = hq[1], ha2 = hq[2], ha3 = hq[3]; hq += 16;

            #pragma unroll 2
            for (int kp = 0; kp < KPAD; kp += 2) {
                // h for kp+1 (B)
                ulonglong2 hb0 = hq[0], hb1 = hq[1], hb2 = hq[2], hb3 = hq[3]; hq += 16;

                // compute kp (A operands)
                row8(acc + 0,  ha0.x, wa0, wa1, wa2, wa3);
                row8(acc + 8,  ha0.y, wa0, wa1, wa2, wa3);
                row8(acc + 16, ha1.x, wa0, wa1, wa2, wa3);
                row8(acc + 24, ha1.y, wa0, wa1, wa2, wa3);
                row8(acc + 32, ha2.x, wa0, wa1, wa2, wa3);
                row8(acc + 40, ha2.y, wa0, wa1, wa2, wa3);
                row8(acc + 48, ha3.x, wa0, wa1, wa2, wa3);
                row8(acc + 56, ha3.y, wa0, wa1, wa2, wa3);

                // prefetch kp+2 (A regs) — pad rows make over-read safe
                wa0 = wq[0]; wa1 = wq[1]; wa2 = wq[2]; wa3 = wq[3]; wq += 128;
                ha0 = hq[0]; ha1 = hq[1]; ha2 = hq[2]; ha3 = hq[3]; hq += 16;

                // compute kp+1 (B operands)
                row8(acc + 0,  hb0.x, wb0, wb1, wb2, wb3);
                row8(acc + 8,  hb0.y, wb0, wb1, wb2, wb3);
                row8(acc + 16, hb1.x, wb0, wb1, wb2, wb3);
                row8(acc + 24, hb1.y, wb0, wb1, wb2, wb3);
                row8(acc + 32, hb2.x, wb0, wb1, wb2, wb3);
                row8(acc + 40, hb2.y, wb0, wb1, wb2, wb3);
                row8(acc + 48, hb3.x, wb0, wb1, wb2, wb3);
                row8(acc + 56, hb3.y, wb0, wb1, wb2, wb3);

                // prefetch kp+3 (B regs)
                wb0 = wq[0]; wb1 = wq[1]; wb2 = wq[2]; wb3 = wq[3]; wq += 128;
            }
        }

        __syncthreads();   // S1: all reads of old h/aug done

        // ---- epilogue: h = relu(lo+hi), store paired h ----
        // thread owns rows r0..r0+7, output pairs (d0>>1)..+3
        #pragma unroll
        for (int j2 = 0; j2 < 4; ++j2) {
            float4* dst = (float4*)(sh + ((d0 >> 1) + j2) * RB + r0);
            #pragma unroll
            for (int i2 = 0; i2 < 4; ++i2) {   // 2 rows per float4
                float a0, b0, a1, b1, a2, b2, a3, b3;
                unpack2(acc[(2 * i2) * 8 + 2 * j2],         a0, b0);
                unpack2(acc[(2 * i2) * 8 + 2 * j2 + 1],     a1, b1);
                unpack2(acc[(2 * i2 + 1) * 8 + 2 * j2],     a2, b2);
                unpack2(acc[(2 * i2 + 1) * 8 + 2 * j2 + 1], a3, b3);
                dst[i2] = make_float4(fmaxf(a0 + b0, 0.f), fmaxf(a1 + b1, 0.f),
                                      fmaxf(a2 + b2, 0.f), fmaxf(a3 + b3, 0.f));
            }
        }
        if (!dec) {   // stage x_{t+1} or SOS (col 10 -> pair 5 = {1,0})
            if (t + 1 < T_) {
                sh[(128 + c1) * RB + r1] = xv1;
                if (tid < 64) sh[(132 + c1) * RB + r1] = xv2;
            } else {
                sh[(128 + c1) * RB + r1] = 0ull;
                if (tid < 64) sh[(132 + c1) * RB + r1] = (c1 == 1) ? pk(1.f, 0.f) : 0ull;
            }
        } else {      // clear previous one-hot
            sh[(128 + c1) * RB + r1] = 0ull;
            if (tid < 64) sh[(132 + c1) * RB + r1] = 0ull;
        }
        __syncthreads();   // S2: new h (+aug/zero) visible

        // ---- decoder: tiled y = h @ Wy^T + by (4 warps), argmax, feedback ----
        if (dec) {
            const int kg = lane & 3;          // k in {kg, kg+4, kg+8}
            const int mg = lane >> 2;         // m-chunk [16*mg, 16*mg+16)
            const int rw = warp * 8;          // 8 rows per warp
            const ull* w0 = sWy + kg * 128;
            const ull* w1 = sWy + (kg + 4) * 128;
            const ull* w2 = sWy + (kg + 8) * 128;
            ull a[24];                         // [row 8][k 3]
            #pragma unroll
            for (int q = 0; q < 24; ++q) a[q] = 0ull;
            const int mbase = mg * 16;
            #pragma unroll 4
            for (int mm = 0; mm < 16; ++mm) {
                const int m = mbase + mm;
                const ulonglong2* hp = (const ulonglong2*)(sh + (size_t)m * RB + rw);
                ulonglong2 h01 = hp[0], h23 = hp[1], h45 = hp[2], h67 = hp[3];
                ull hr[8] = {h01.x, h01.y, h23.x, h23.y, h45.x, h45.y, h67.x, h67.y};
                ull wv0 = w0[m], wv1 = w1[m], wv2 = w2[m];
                #pragma unroll
                for (int i = 0; i < 8; ++i) {
                    ffma2(a[i * 3 + 0], hr[i], wv0);
                    ffma2(a[i * 3 + 1], hr[i], wv1);
                    ffma2(a[i * 3 + 2], hr[i], wv2);
                }
            }
            float v[24];
            #pragma unroll
            for (int q = 0; q < 24; ++q) {
                float lo, hi; unpack2(a[q], lo, hi);
                v[q] = lo + hi;
            }
            #pragma unroll
            for (int q = 0; q < 24; ++q) {
                v[q] += shflx(v[q], 4);
                v[q] += shflx(v[q], 8);
                v[q] += shflx(v[q], 16);
            }
            if (mg == 0) {
                #pragma unroll
                for (int i = 0; i < 8; ++i) {
                    yt[(rw + i) * 12 + kg]     = v[i * 3 + 0] + sby[kg];
                    yt[(rw + i) * 12 + kg + 4] = v[i * 3 + 1] + sby[kg + 4];
                    yt[(rw + i) * 12 + kg + 8] = v[i * 3 + 2] + sby[kg + 8];
                }
            }
            __syncthreads();   // yt complete
            if (tid < 32) {
                const float* yr = yt + tid * 12;
                float vv[12];
                #pragma unroll
                for (int q = 0; q < 3; ++q) {
                    float4 fv = *(const float4*)(yr + 4 * q);
                    vv[4 * q] = fv.x; vv[4 * q + 1] = fv.y;
                    vv[4 * q + 2] = fv.z; vv[4 * q + 3] = fv.w;
                }
                float best = vv[0]; int sel = 0;
                #pragma unroll
                for (int q = 1; q < 12; ++q)
                    if (vv[q] > best) { best = vv[q]; sel = q; }   // first-max wins
                float* og = out + ((size_t)(t - T_) * N_ + rowbase + tid) * K_;
                *(float4*)(og)     = make_float4(vv[0], vv[1], vv[2],  vv[3]);
                *(float4*)(og + 4) = make_float4(vv[4], vv[5], vv[6],  vv[7]);
                *(float4*)(og + 8) = make_float4(vv[8], vv[9], vv[10], vv[11]);
                sh[(128 + (sel >> 1)) * RB + tid] = (sel & 1) ? pk(0.f, 1.f) : pk(1.f, 0.f);
            }
            __syncthreads();   // one-hot visible before next step's reads
        }
    }
}

extern "C" void kernel_launch(void* const* d_in, const int* in_sizes, int n_in,
                              void* d_out, int out_size) {
    const float* x   = (const float*)d_in[0];
    const float* eWx = (const float*)d_in[1];
    const float* ebx = (const float*)d_in[2];
    const float* eWh = (const float*)d_in[3];
    const float* dWx = (const float*)d_in[6];
    const float* dbx = (const float*)d_in[7];
    const float* dWh = (const float*)d_in[8];
    const float* dWy = (const float*)d_in[9];
    const float* dby = (const float*)d_in[10];

    prep_kernel<<<2 * KPP, D_>>>(eWh, eWx, dWh, dWx);

    cudaFuncSetAttribute(seq2seq_kernel,
                         cudaFuncAttributeMaxDynamicSharedMemorySize, SMEM_BYTES);
    seq2seq_kernel<<<NBLK, NTHR, SMEM_BYTES>>>(
        x, ebx, dbx, dWy, dby, (float*)d_out);
}

// round 10
// speedup vs baseline: 1.0957x; 1.0007x over previous
#include <cuda_runtime.h>
#include <cstdint>

#define T_    256
#define N_    4096
#define C_    12
#define D_    256
#define K_    12
#define KPAD  136          // 272/2 k-pairs: 128 h + 6 x/onehot + 2 pad
#define KPP   (KPAD + 2)   // padded for prefetch over-read
#define RB    32
#define NTHR  128
#define NBLK  (N_ / RB)    // 128

typedef unsigned long long ull;

// ---- smem layout (ull units) ----
#define U_SH   0                       // h_aug [(KPAD+2)][32] ull
#define U_WY   (U_SH + KPP * RB)       // Wy paired [12][128] ull
#define U_BE   (U_WY + 12 * 128)       // enc bias {b,0} [256]
#define U_BD   (U_BE + 256)            // dec bias {b,0} [256]
#define U_YT   (U_BD + 256)            // ytmp 384 floats = 192 ull
#define U_BY   (U_YT + 192)            // by 12 floats (pad 16)
#define U_TOT  (U_BY + 8)
#define SMEM_BYTES (U_TOT * 8)         // ~53 KB

// W pre-paired: g_Wp[phase][kp][d] = {W(d,2kp), W(d,2kp+1)}; kp>=128 -> Wx cols; kp>=134 -> 0
// 2 pad kp rows per phase so depth-2 prefetch can over-read safely.
__device__ float2 g_Wp[2][KPP][D_];

__device__ __forceinline__ void ffma2(ull &d, ull a, ull b) {
    asm("fma.rn.f32x2 %0, %1, %2, %0;" : "+l"(d) : "l"(a), "l"(b));
}
__device__ __forceinline__ void unpack2(ull v, float &lo, float &hi) {
    asm("mov.b64 {%0, %1}, %2;" : "=f"(lo), "=f"(hi) : "l"(v));
}
__device__ __forceinline__ ull pk(float a, float b) {
    ull r; asm("mov.b64 %0, {%1, %2};" : "=l"(r) : "f"(a), "f"(b)); return r;
}
__device__ __forceinline__ float shflx(float v, int m) {
    float r;
    asm("shfl.sync.bfly.b32 %0, %1, %2, 0x1f, 0xffffffff;" : "=f"(r) : "f"(v), "r"(m));
    return r;
}
// one h value (duplicated k-pair for one row) times 8 outputs
__device__ __forceinline__ void row8(ull* a, ull h,
                                     const ulonglong2 &w0, const ulonglong2 &w1,
                                     const ulonglong2 &w2, const ulonglong2 &w3) {
    ffma2(a[0], h, w0.x); ffma2(a[1], h, w0.y);
    ffma2(a[2], h, w1.x); ffma2(a[3], h, w1.y);
    ffma2(a[4], h, w2.x); ffma2(a[5], h, w2.y);
    ffma2(a[6], h, w3.x); ffma2(a[7], h, w3.y);
}

// ---------------- prep: paired fused weight image ----------------
__global__ void prep_kernel(const float* __restrict__ eWh, const float* __restrict__ eWx,
                            const float* __restrict__ dWh, const float* __restrict__ dWx)
{
    int p  = blockIdx.x / KPP;
    int kp = blockIdx.x % KPP;
    int d  = threadIdx.x;
    const float* Wh = p ? dWh : eWh;
    const float* Wx = p ? dWx : eWx;
    int k0 = 2 * kp, k1 = 2 * kp + 1;
    float v0 = (k0 < D_) ? Wh[d * D_ + k0] : ((k0 < D_ + C_) ? Wx[d * C_ + (k0 - D_)] : 0.f);
    float v1 = (k1 < D_) ? Wh[d * D_ + k1] : ((k1 < D_ + C_) ? Wx[d * C_ + (k1 - D_)] : 0.f);
    g_Wp[p][kp][d] = make_float2(v0, v1);   // pad rows (kp>=134) are 0
}

// ---------------- main persistent kernel ----------------
extern "C" __global__ void __launch_bounds__(NTHR, 1)
seq2seq_kernel(const float* __restrict__ x,
               const float* __restrict__ ebx, const float* __restrict__ dbx,
               const float* __restrict__ dWy, const float* __restrict__ dby,
               float* __restrict__ out)
{
    extern __shared__ ull smu[];
    ull*   sh  = smu + U_SH;
    ull*   sWy = smu + U_WY;
    ull*   sbe = smu + U_BE;
    ull*   sbd = smu + U_BD;
    float* yt  = (float*)(smu + U_YT);
    float* sby = (float*)(smu + U_BY);

    const int tid  = threadIdx.x;
    const int lane = tid & 31;
    const int warp = tid >> 5;
    const int r0   = (tid & 3) * 8;       // 8 rows
    const int d0   = (tid >> 2) * 8;      // 8 outputs (ull index == output index)
    const int rowbase = blockIdx.x * RB;

    const int c1 = tid >> 5;              // aug staging: pair-col (slot tid), row
    const int r1 = tid & 31;

    // ---- init ----
    for (int i = tid; i < KPP * RB; i += NTHR) sh[i] = 0ull;
    for (int i = tid; i < 12 * 128; i += NTHR) sWy[i] = ((const ull*)dWy)[i];
    for (int i = tid; i < D_; i += NTHR) {
        sbe[i] = pk(ebx[i], 0.f);
        sbd[i] = pk(dbx[i], 0.f);
    }
    if (tid < K_) sby[tid] = dby[tid];
    __syncthreads();

    // stage x_0 into aug rows (192 slots: tid, and tid+128 for tid<64)
    {
        const float2 a = *(const float2*)(x + ((size_t)rowbase + r1) * C_ + 2 * c1);
        sh[(128 + c1) * RB + r1] = pk(a.x, a.y);
        if (tid < 64) {
            const float2 b = *(const float2*)(x + ((size_t)rowbase + r1) * C_ + 2 * (4 + c1));
            sh[(132 + c1) * RB + r1] = pk(b.x, b.y);
        }
    }
    __syncthreads();

    // per-thread W pointers (ulonglong2 units); kp stride = D_/2 = 128 ull2
    const ulonglong2* const wbase0 = (const ulonglong2*)&g_Wp[0][0][0] + (d0 >> 1);
    const ulonglong2* const wbase1 = (const ulonglong2*)&g_Wp[1][0][0] + (d0 >> 1);

    ull acc[64];

    for (int t = 0; t < 2 * T_; ++t) {
        const bool dec = (t >= T_);

        // prefetch next x slice into regs (encoder)
        ull xv1 = 0ull, xv2 = 0ull;
        if (!dec && (t + 1) < T_) {
            const float2 a = *(const float2*)(x + ((size_t)(t + 1) * N_ + rowbase + r1) * C_ + 2 * c1);
            xv1 = pk(a.x, a.y);
            if (tid < 64) {
                const float2 b = *(const float2*)(x + ((size_t)(t + 1) * N_ + rowbase + r1) * C_ + 2 * (4 + c1));
                xv2 = pk(b.x, b.y);
            }
        }

        // acc init = {bias, 0}
        {
            const ulonglong2* bp = (const ulonglong2*)((dec ? sbd : sbe) + d0);
            ulonglong2 b01 = bp[0], b23 = bp[1], b45 = bp[2], b67 = bp[3];
            ull bj[8] = {b01.x, b01.y, b23.x, b23.y, b45.x, b45.y, b67.x, b67.y};
            #pragma unroll
            for (int i = 0; i < 8; ++i)
                #pragma unroll
                for (int j = 0; j < 8; ++j) acc[i * 8 + j] = bj[j];
        }

        // ---- GEMM: flat kp loop; W depth-2 LDG prefetch, h depth-1 LDS ----
        {
            const ulonglong2* wq = dec ? wbase1 : wbase0;
            const ulonglong2* hq = (const ulonglong2*)(sh + r0);

            // prime: W for kp0 (A), kp1 (B); h for kp0 (A)
            ulonglong2 wa0 = wq[0], wa1 = wq[1], wa2 = wq[2], wa3 = wq[3]; wq += 128;
            ulonglong2 wb0 = wq[0], wb1 = wq[1], wb2 = wq[2], wb3 = wq[3]; wq += 128;
            ulonglong2 ha0 = hq[0], ha1 = hq[1], ha2 = hq[2], ha3 = hq[3]; hq += 16;

            #pragma unroll 2
            for (int kp = 0; kp < KPAD; kp += 2) {
                // h for kp+1 (B)
                ulonglong2 hb0 = hq[0], hb1 = hq[1], hb2 = hq[2], hb3 = hq[3]; hq += 16;

                // compute kp (A operands)
                row8(acc + 0,  ha0.x, wa0, wa1, wa2, wa3);
                row8(acc + 8,  ha0.y, wa0, wa1, wa2, wa3);
                row8(acc + 16, ha1.x, wa0, wa1, wa2, wa3);
                row8(acc + 24, ha1.y, wa0, wa1, wa2, wa3);
                row8(acc + 32, ha2.x, wa0, wa1, wa2, wa3);
                row8(acc + 40, ha2.y, wa0, wa1, wa2, wa3);
                row8(acc + 48, ha3.x, wa0, wa1, wa2, wa3);
                row8(acc + 56, ha3.y, wa0, wa1, wa2, wa3);

                // prefetch kp+2 (A regs) — pad rows make over-read safe
                wa0 = wq[0]; wa1 = wq[1]; wa2 = wq[2]; wa3 = wq[3]; wq += 128;
                ha0 = hq[0]; ha1 = hq[1]; ha2 = hq[2]; ha3 = hq[3]; hq += 16;

                // compute kp+1 (B operands)
                row8(acc + 0,  hb0.x, wb0, wb1, wb2, wb3);
                row8(acc + 8,  hb0.y, wb0, wb1, wb2, wb3);
                row8(acc + 16, hb1.x, wb0, wb1, wb2, wb3);
                row8(acc + 24, hb1.y, wb0, wb1, wb2, wb3);
                row8(acc + 32, hb2.x, wb0, wb1, wb2, wb3);
                row8(acc + 40, hb2.y, wb0, wb1, wb2, wb3);
                row8(acc + 48, hb3.x, wb0, wb1, wb2, wb3);
                row8(acc + 56, hb3.y, wb0, wb1, wb2, wb3);

                // prefetch kp+3 (B regs)
                wb0 = wq[0]; wb1 = wq[1]; wb2 = wq[2]; wb3 = wq[3]; wq += 128;
            }
        }

        __syncthreads();   // S1: all reads of old h/aug done

        // ---- epilogue: h = relu(lo+hi), store paired h ----
        // thread owns rows r0..r0+7, output pairs (d0>>1)..+3
        #pragma unroll
        for (int j2 = 0; j2 < 4; ++j2) {
            float4* dst = (float4*)(sh + ((d0 >> 1) + j2) * RB + r0);
            #pragma unroll
            for (int i2 = 0; i2 < 4; ++i2) {   // 2 rows per float4
                float a0, b0, a1, b1, a2, b2, a3, b3;
                unpack2(acc[(2 * i2) * 8 + 2 * j2],         a0, b0);
                unpack2(acc[(2 * i2) * 8 + 2 * j2 + 1],     a1, b1);
                unpack2(acc[(2 * i2 + 1) * 8 + 2 * j2],     a2, b2);
                unpack2(acc[(2 * i2 + 1) * 8 + 2 * j2 + 1], a3, b3);
                dst[i2] = make_float4(fmaxf(a0 + b0, 0.f), fmaxf(a1 + b1, 0.f),
                                      fmaxf(a2 + b2, 0.f), fmaxf(a3 + b3, 0.f));
            }
        }
        if (!dec) {   // stage x_{t+1} or SOS (col 10 -> pair 5 = {1,0})
            if (t + 1 < T_) {
                sh[(128 + c1) * RB + r1] = xv1;
                if (tid < 64) sh[(132 + c1) * RB + r1] = xv2;
            } else {
                sh[(128 + c1) * RB + r1] = 0ull;
                if (tid < 64) sh[(132 + c1) * RB + r1] = (c1 == 1) ? pk(1.f, 0.f) : 0ull;
            }
        } else {      // clear previous one-hot
            sh[(128 + c1) * RB + r1] = 0ull;
            if (tid < 64) sh[(132 + c1) * RB + r1] = 0ull;
        }
        __syncthreads();   // S2: new h (+aug/zero) visible

        // ---- decoder: tiled y = h @ Wy^T + by (4 warps), argmax, feedback ----
        if (dec) {
            const int kg = lane & 3;          // k in {kg, kg+4, kg+8}
            const int mg = lane >> 2;         // m-chunk [16*mg, 16*mg+16)
            const int rw = warp * 8;          // 8 rows per warp
            const ull* w0 = sWy + kg * 128;
            const ull* w1 = sWy + (kg + 4) * 128;
            const ull* w2 = sWy + (kg + 8) * 128;
            ull a[24];                         // [row 8][k 3]
            #pragma unroll
            for (int q = 0; q < 24; ++q) a[q] = 0ull;
            const int mbase = mg * 16;
            #pragma unroll 4
            for (int mm = 0; mm < 16; ++mm) {
                const int m = mbase + mm;
                const ulonglong2* hp = (const ulonglong2*)(sh + (size_t)m * RB + rw);
                ulonglong2 h01 = hp[0], h23 = hp[1], h45 = hp[2], h67 = hp[3];
                ull hr[8] = {h01.x, h01.y, h23.x, h23.y, h45.x, h45.y, h67.x, h67.y};
                ull wv0 = w0[m], wv1 = w1[m], wv2 = w2[m];
                #pragma unroll
                for (int i = 0; i < 8; ++i) {
                    ffma2(a[i * 3 + 0], hr[i], wv0);
                    ffma2(a[i * 3 + 1], hr[i], wv1);
                    ffma2(a[i * 3 + 2], hr[i], wv2);
                }
            }
            float v[24];
            #pragma unroll
            for (int q = 0; q < 24; ++q) {
                float lo, hi; unpack2(a[q], lo, hi);
                v[q] = lo + hi;
            }
            #pragma unroll
            for (int q = 0; q < 24; ++q) {
                v[q] += shflx(v[q], 4);
                v[q] += shflx(v[q], 8);
                v[q] += shflx(v[q], 16);
            }
            if (mg == 0) {
                #pragma unroll
                for (int i = 0; i < 8; ++i) {
                    yt[(rw + i) * 12 + kg]     = v[i * 3 + 0] + sby[kg];
                    yt[(rw + i) * 12 + kg + 4] = v[i * 3 + 1] + sby[kg + 4];
                    yt[(rw + i) * 12 + kg + 8] = v[i * 3 + 2] + sby[kg + 8];
                }
            }
            __syncthreads();   // yt complete
            if (tid < 32) {
                const float* yr = yt + tid * 12;
                float vv[12];
                #pragma unroll
                for (int q = 0; q < 3; ++q) {
                    float4 fv = *(const float4*)(yr + 4 * q);
                    vv[4 * q] = fv.x; vv[4 * q + 1] = fv.y;
                    vv[4 * q + 2] = fv.z; vv[4 * q + 3] = fv.w;
                }
                float best = vv[0]; int sel = 0;
                #pragma unroll
                for (int q = 1; q < 12; ++q)
                    if (vv[q] > best) { best = vv[q]; sel = q; }   // first-max wins
                float* og = out + ((size_t)(t - T_) * N_ + rowbase + tid) * K_;
                *(float4*)(og)     = make_float4(vv[0], vv[1], vv[2],  vv[3]);
                *(float4*)(og + 4) = make_float4(vv[4], vv[5], vv[6],  vv[7]);
                *(float4*)(og + 8) = make_float4(vv[8], vv[9], vv[10], vv[11]);
                sh[(128 + (sel >> 1)) * RB + tid] = (sel & 1) ? pk(0.f, 1.f) : pk(1.f, 0.f);
            }
            __syncthreads();   // one-hot visible before next step's reads
        }
    }
}

extern "C" void kernel_launch(void* const* d_in, const int* in_sizes, int n_in,
                              void* d_out, int out_size) {
    const float* x   = (const float*)d_in[0];
    const float* eWx = (const float*)d_in[1];
    const float* ebx = (const float*)d_in[2];
    const float* eWh = (const float*)d_in[3];
    const float* dWx = (const float*)d_in[6];
    const float* dbx = (const float*)d_in[7];
    const float* dWh = (const float*)d_in[8];
    const float* dWy = (const float*)d_in[9];
    const float* dby = (const float*)d_in[10];

    prep_kernel<<<2 * KPP, D_>>>(eWh, eWx, dWh, dWx);

    cudaFuncSetAttribute(seq2seq_kernel,
                         cudaFuncAttributeMaxDynamicSharedMemorySize, SMEM_BYTES);
    seq2seq_kernel<<<NBLK, NTHR, SMEM_BYTES>>>(
        x, ebx, dbx, dWy, dby, (float*)d_out);
}

// round 11
// speedup vs baseline: 1.1316x; 1.0328x over previous
#include <cuda_runtime.h>
#include <cstdint>

#define T_    256
#define N_    4096
#define C_    12
#define D_    256
#define K_    12
#define KPAD  136          // 272/2 k-pairs: 128 h + 6 x/onehot + 2 zero pad
#define RB    32
#define NTHR  256
#define NBLK  (N_ / RB)    // 128
#define CH    34           // k-pairs per TMA chunk; 4 chunks = 136
#define NCHK  4
#define CHW   (CH * D_)    // ull per chunk (8704)
#define CHBYTES (CHW * 8)  // 69632
#define GTOT  (2 * T_ * NCHK)   // 2048

typedef unsigned long long ull;

// ---- smem layout (ull units) ----
#define U_W    0                       // 2 chunk buffers: 17408
#define U_SH0  (U_W + 2 * CHW)         // h_aug buf0 [136][32]
#define U_SH1  (U_SH0 + KPAD * RB)     // h_aug buf1
#define U_WY   (U_SH1 + KPAD * RB)     // Wy paired [12][128]
#define U_BE   (U_WY + 12 * 128)       // enc bias {b,0} [256]
#define U_BD   (U_BE + 256)            // dec bias {b,0} [256]
#define U_YT   (U_BD + 256)            // ytmp 384 floats = 192 ull
#define U_BY   (U_YT + 192)            // by 12 floats (pad 16)
#define U_MB   (U_BY + 8)              // 2 mbarriers
#define U_TOT  (U_MB + 2)
#define SMEM_BYTES (U_TOT * 8)         // 226,896 B

// W pre-paired: g_Wp[phase][kp][d] = {W(d,2kp), W(d,2kp+1)}; kp>=128 -> Wx cols; kp>=134 -> 0
__device__ float2 g_Wp[2][KPAD][D_];

__device__ __forceinline__ void ffma2(ull &d, ull a, ull b) {
    asm("fma.rn.f32x2 %0, %1, %2, %0;" : "+l"(d) : "l"(a), "l"(b));
}
__device__ __forceinline__ void unpack2(ull v, float &lo, float &hi) {
    asm("mov.b64 {%0, %1}, %2;" : "=f"(lo), "=f"(hi) : "l"(v));
}
__device__ __forceinline__ ull pk(float a, float b) {
    ull r; asm("mov.b64 %0, {%1, %2};" : "=l"(r) : "f"(a), "f"(b)); return r;
}
__device__ __forceinline__ float shflx(float v, int m) {
    float r;
    asm("shfl.sync.bfly.b32 %0, %1, %2, 0x1f, 0xffffffff;" : "=f"(r) : "f"(v), "r"(m));
    return r;
}
__device__ __forceinline__ unsigned smem_u32(const void* p) {
    unsigned r;
    asm("{ .reg .u64 t; cvta.to.shared.u64 t, %1; cvt.u32.u64 %0, t; }" : "=r"(r) : "l"(p));
    return r;
}
__device__ __forceinline__ void mbar_init(unsigned mb, unsigned cnt) {
    asm volatile("mbarrier.init.shared.b64 [%0], %1;" :: "r"(mb), "r"(cnt) : "memory");
}
__device__ __forceinline__ void mbar_wait(unsigned mb, unsigned parity) {
    unsigned done;
    asm volatile("{\n\t.reg .pred p;\n\t"
                 "mbarrier.try_wait.parity.acquire.cta.shared::cta.b64 p, [%1], %2;\n\t"
                 "selp.b32 %0, 1, 0, p;\n\t}"
                 : "=r"(done) : "r"(mb), "r"(parity) : "memory");
    if (!done) {
        asm volatile("{\n\t.reg .pred P;\n"
                     "W%=:\n\t"
                     "mbarrier.try_wait.parity.acquire.cta.shared::cta.b64 P, [%0], %1, 0x989680;\n\t"
                     "@P bra.uni D%=;\n\t"
                     "bra.uni W%=;\n"
                     "D%=:\n\t}"
                     :: "r"(mb), "r"(parity) : "memory");
    }
}
__device__ __forceinline__ void tma_issue(unsigned mb, unsigned dst, const void* src) {
    asm volatile("mbarrier.arrive.expect_tx.shared.b64 _, [%0], %1;"
                 :: "r"(mb), "r"((unsigned)CHBYTES) : "memory");
    asm volatile("cp.async.bulk.shared::cluster.global.mbarrier::complete_tx::bytes "
                 "[%0], [%1], %2, [%3];"
                 :: "r"(dst), "l"(src), "r"((unsigned)CHBYTES), "r"(mb) : "memory");
}

// ---------------- prep: paired fused weight image ----------------
__global__ void prep_kernel(const float* __restrict__ eWh, const float* __restrict__ eWx,
                            const float* __restrict__ dWh, const float* __restrict__ dWx)
{
    int p  = blockIdx.x / KPAD;
    int kp = blockIdx.x % KPAD;
    int d  = threadIdx.x;
    const float* Wh = p ? dWh : eWh;
    const float* Wx = p ? dWx : eWx;
    int k0 = 2 * kp, k1 = 2 * kp + 1;
    float v0 = (k0 < D_) ? Wh[d * D_ + k0] : ((k0 < D_ + C_) ? Wx[d * C_ + (k0 - D_)] : 0.f);
    float v1 = (k1 < D_) ? Wh[d * D_ + k1] : ((k1 < D_ + C_) ? Wx[d * C_ + (k1 - D_)] : 0.f);
    g_Wp[p][kp][d] = make_float2(v0, v1);
}

// ---------------- main persistent kernel ----------------
extern "C" __global__ void __launch_bounds__(NTHR, 1)
seq2seq_kernel(const float* __restrict__ x,
               const float* __restrict__ ebx, const float* __restrict__ dbx,
               const float* __restrict__ dWy, const float* __restrict__ dby,
               float* __restrict__ out)
{
    extern __shared__ ull smu[];
    ull*   smW = smu + U_W;
    ull*   sh0 = smu + U_SH0;
    ull*   sh1 = smu + U_SH1;
    ull*   sWy = smu + U_WY;
    ull*   sbe = smu + U_BE;
    ull*   sbd = smu + U_BD;
    float* yt  = (float*)(smu + U_YT);
    float* sby = (float*)(smu + U_BY);

    const int tid  = threadIdx.x;
    const int lane = tid & 31;
    const int warp = tid >> 5;
    const int r0   = (tid & 7) * 4;       // 4 rows
    const int d0   = (tid >> 3) * 8;      // 8 outputs (ull index == output index)
    const int rowbase = blockIdx.x * RB;

    const unsigned sW_u32 = smem_u32(smu) + U_W * 8;
    const unsigned mb_u32 = smem_u32(smu) + U_MB * 8;

    const int c1 = tid >> 5;              // aug staging (tid<192): pair-col, row
    const int r1 = tid & 31;

    // ---- init ----
    for (int i = tid; i < 2 * KPAD * RB; i += NTHR) sh0[i] = 0ull;   // covers sh1 too
    for (int i = tid; i < 12 * 128; i += NTHR) sWy[i] = ((const ull*)dWy)[i];
    for (int i = tid; i < D_; i += NTHR) {
        sbe[i] = pk(ebx[i], 0.f);
        sbd[i] = pk(dbx[i], 0.f);
    }
    if (tid < K_) sby[tid] = dby[tid];
    if (tid == 0) { mbar_init(mb_u32, 1); mbar_init(mb_u32 + 8, 1); }
    __syncthreads();

    // stage x_0 into buf0 aug rows (192 slots)
    if (tid < 192) {
        const float2 a = *(const float2*)(x + ((size_t)rowbase + r1) * C_ + 2 * c1);
        sh0[(128 + c1) * RB + r1] = pk(a.x, a.y);
    }
    if (tid == 0) {   // prime chunks g=0 (buf0), g=1 (buf1), phase 0
        tma_issue(mb_u32,     sW_u32,           (const char*)g_Wp);
        tma_issue(mb_u32 + 8, sW_u32 + CHBYTES, (const char*)g_Wp + (size_t)CH * D_ * 8);
    }
    __syncthreads();

    ull acc[32];

    for (int t = 0; t < 2 * T_; ++t) {
        const bool dec = (t >= T_);
        ull* cur = (t & 1) ? sh1 : sh0;
        ull* nxt = (t & 1) ? sh0 : sh1;

        // prefetch next x slice into regs (encoder)
        ull xv = 0ull;
        if (!dec && (t + 1) < T_ && tid < 192) {
            const float2 a = *(const float2*)(x + ((size_t)(t + 1) * N_ + rowbase + r1) * C_ + 2 * c1);
            xv = pk(a.x, a.y);
        }

        // acc init = {bias, 0}
        {
            const ulonglong2* bp = (const ulonglong2*)((dec ? sbd : sbe) + d0);
            ulonglong2 b01 = bp[0], b23 = bp[1], b45 = bp[2], b67 = bp[3];
            ull bj[8] = {b01.x, b01.y, b23.x, b23.y, b45.x, b45.y, b67.x, b67.y};
            #pragma unroll
            for (int i = 0; i < 4; ++i)
                #pragma unroll
                for (int j = 0; j < 8; ++j) acc[i * 8 + j] = bj[j];
        }

        // ---- GEMM: 4 chunks of 34 kp, TMA double-buffered ----
        #pragma unroll 1
        for (int c = 0; c < NCHK; ++c) {
            const int g   = t * NCHK + c;
            const int b   = g & 1;
            const unsigned par = (unsigned)((g >> 1) & 1);
            mbar_wait(mb_u32 + b * 8, par);

            const ull* wb = smW + (size_t)b * CHW + d0;
            const ull* hb = cur + (size_t)(c * CH) * RB + r0;

            #pragma unroll 2
            for (int kk = 0; kk < CH; ++kk) {
                const ulonglong2* hp = (const ulonglong2*)(hb + (size_t)kk * RB);
                ulonglong2 hA = hp[0], hB = hp[1];
                const ulonglong2* wp = (const ulonglong2*)(wb + (size_t)kk * D_);
                ulonglong2 w01 = wp[0], w23 = wp[1], w45 = wp[2], w67 = wp[3];
                ull hr[4] = {hA.x, hA.y, hB.x, hB.y};
                ull wr[8] = {w01.x, w01.y, w23.x, w23.y, w45.x, w45.y, w67.x, w67.y};
                #pragma unroll
                for (int i = 0; i < 4; ++i)
                    #pragma unroll
                    for (int j = 0; j < 8; ++j)
                        ffma2(acc[i * 8 + j], hr[i], wr[j]);
            }
            __syncthreads();   // buffer b consumed by all threads

            if (tid == 0 && (g + 2) < GTOT) {
                const int g2 = g + 2;
                const int t2 = g2 >> 2, c2 = g2 & 3;
                const int ph = (t2 >= T_) ? 1 : 0;
                tma_issue(mb_u32 + b * 8, sW_u32 + b * CHBYTES,
                          (const char*)g_Wp + ((size_t)ph * KPAD + c2 * CH) * D_ * 8);
            }
        }

        // ---- epilogue: h = relu(lo+hi), store paired h into NXT ----
        #pragma unroll
        for (int j2 = 0; j2 < 4; ++j2) {
            float4* dst = (float4*)(nxt + (size_t)((d0 >> 1) + j2) * RB + r0);
            #pragma unroll
            for (int i2 = 0; i2 < 2; ++i2) {
                float a0, b0, a1, b1, a2, b2, a3, b3;
                unpack2(acc[(2 * i2) * 8 + 2 * j2],         a0, b0);
                unpack2(acc[(2 * i2) * 8 + 2 * j2 + 1],     a1, b1);
                unpack2(acc[(2 * i2 + 1) * 8 + 2 * j2],     a2, b2);
                unpack2(acc[(2 * i2 + 1) * 8 + 2 * j2 + 1], a3, b3);
                dst[i2] = make_float4(fmaxf(a0 + b0, 0.f), fmaxf(a1 + b1, 0.f),
                                      fmaxf(a2 + b2, 0.f), fmaxf(a3 + b3, 0.f));
            }
        }
        if (!dec && tid < 192) {
            // stage x_{t+1} or SOS (col 10 -> pair 5 = {1,0}) into NXT aug
            nxt[(128 + c1) * RB + r1] =
                (t + 1 < T_) ? xv : ((c1 == 5) ? pk(1.f, 0.f) : 0ull);
        }
        __syncthreads();   // publish new h (+aug)

        // ---- decoder: tiled y = h @ Wy^T + by, argmax, one-hot feedback ----
        if (dec) {
            const int kg = lane & 3;          // k in {kg, kg+4, kg+8}
            const int mg = lane >> 2;         // m-chunk [16*mg, 16*mg+16)
            const ull* hb = nxt + 4 * warp;   // rows 4*warp..+3 of NEW h
            const ull* w0 = sWy + kg * 128;
            const ull* w1 = sWy + (kg + 4) * 128;
            const ull* w2 = sWy + (kg + 8) * 128;
            ull a[12];
            #pragma unroll
            for (int q = 0; q < 12; ++q) a[q] = 0ull;
            const int mbase = mg * 16;
            #pragma unroll 4
            for (int mm = 0; mm < 16; ++mm) {
                const int m = mbase + mm;
                const ulonglong2* hp = (const ulonglong2*)(hb + (size_t)m * RB);
                ulonglong2 hA = hp[0], hB = hp[1];
                ull hr[4] = {hA.x, hA.y, hB.x, hB.y};
                ull wv0 = w0[m], wv1 = w1[m], wv2 = w2[m];
                #pragma unroll
                for (int i = 0; i < 4; ++i) {
                    ffma2(a[i * 3 + 0], hr[i], wv0);
                    ffma2(a[i * 3 + 1], hr[i], wv1);
                    ffma2(a[i * 3 + 2], hr[i], wv2);
                }
            }
            float v[12];
            #pragma unroll
            for (int q = 0; q < 12; ++q) {
                float lo, hi; unpack2(a[q], lo, hi);
                v[q] = lo + hi;
            }
            #pragma unroll
            for (int q = 0; q < 12; ++q) {
                v[q] += shflx(v[q], 4);
                v[q] += shflx(v[q], 8);
                v[q] += shflx(v[q], 16);
            }
            if (mg == 0) {
                #pragma unroll
                for (int i = 0; i < 4; ++i) {
                    yt[(4 * warp + i) * 12 + kg]     = v[i * 3 + 0] + sby[kg];
                    yt[(4 * warp + i) * 12 + kg + 4] = v[i * 3 + 1] + sby[kg + 4];
                    yt[(4 * warp + i) * 12 + kg + 8] = v[i * 3 + 2] + sby[kg + 8];
                }
            }
            __syncthreads();   // yt complete
            if (tid < 32) {
                const float* yr = yt + tid * 12;
                float vv[12];
                #pragma unroll
                for (int q = 0; q < 3; ++q) {
                    float4 fv = *(const float4*)(yr + 4 * q);
                    vv[4 * q] = fv.x; vv[4 * q + 1] = fv.y;
                    vv[4 * q + 2] = fv.z; vv[4 * q + 3] = fv.w;
                }
                float best = vv[0]; int sel = 0;
                #pragma unroll
                for (int q = 1; q < 12; ++q)
                    if (vv[q] > best) { best = vv[q]; sel = q; }   // first-max wins
                float* og = out + ((size_t)(t - T_) * N_ + rowbase + tid) * K_;
                *(float4*)(og)     = make_float4(vv[0], vv[1], vv[2],  vv[3]);
                *(float4*)(og + 4) = make_float4(vv[4], vv[5], vv[6],  vv[7]);
                *(float4*)(og + 8) = make_float4(vv[8], vv[9], vv[10], vv[11]);
                // write NXT aug: zero all 6 pair-cols for this row, set one-hot.
                // Visible to next step's chunk-3 reads via 3 intervening chunk barriers.
                const ull oh = (sel & 1) ? pk(0.f, 1.f) : pk(1.f, 0.f);
                #pragma unroll
                for (int cc = 0; cc < 6; ++cc)
                    nxt[(128 + cc) * RB + tid] = (cc == (sel >> 1)) ? oh : 0ull;
            }
            // no trailing barrier: warp0 joins chunk-0 barrier of next step
        }
    }
}

extern "C" void kernel_launch(void* const* d_in, const int* in_sizes, int n_in,
                              void* d_out, int out_size) {
    const float* x   = (const float*)d_in[0];
    const float* eWx = (const float*)d_in[1];
    const float* ebx = (const float*)d_in[2];
    const float* eWh = (const float*)d_in[3];
    const float* dWx = (const float*)d_in[6];
    const float* dbx = (const float*)d_in[7];
    const float* dWh = (const float*)d_in[8];
    const float* dWy = (const float*)d_in[9];
    const float* dby = (const float*)d_in[10];

    prep_kernel<<<2 * KPAD, D_>>>(eWh, eWx, dWh, dWx);

    cudaFuncSetAttribute(seq2seq_kernel,
                         cudaFuncAttributeMaxDynamicSharedMemorySize, SMEM_BYTES);
    seq2seq_kernel<<<NBLK, NTHR, SMEM_BYTES>>>(
        x, ebx, dbx, dWy, dby, (float*)d_out);
}

// round 12
// speedup vs baseline: 1.1800x; 1.0428x over previous
#include <cuda_runtime.h>
#include <cstdint>

#define T_    256
#define N_    4096
#define C_    12
#define D_    256
#define K_    12
#define KPAD  136          // 272/2 k-pairs: 128 h + 6 x/onehot + 2 zero pad
#define RB    32
#define NTHR  128
#define NBLK  (N_ / RB)    // 128
#define CH    34           // k-pairs per TMA chunk; 4 chunks = 136
#define NCHK  4
#define CHW   (CH * D_)    // ull per chunk (8704)
#define CHBYTES (CHW * 8)  // 69632
#define GTOT  (2 * T_ * NCHK)   // 2048
#define HROWS (KPAD + 1)   // 1 pad row absorbs pipeline over-read

typedef unsigned long long ull;

// ---- smem layout (ull units) ----
#define U_W    0                       // 2 chunk buffers: 17408
#define U_SH0  (U_W + 2 * CHW)         // h_aug buf0 [137][32]
#define U_SH1  (U_SH0 + HROWS * RB)    // h_aug buf1
#define U_WY   (U_SH1 + HROWS * RB)    // Wy paired [12][128]
#define U_BE   (U_WY + 12 * 128)       // enc bias {b,0} [256]
#define U_BD   (U_BE + 256)            // dec bias {b,0} [256]
#define U_YT   (U_BD + 256)            // ytmp 384 floats = 192 ull
#define U_BY   (U_YT + 192)            // by 12 floats (pad 16)
#define U_MB   (U_BY + 8)              // 2 mbarriers
#define U_TOT  (U_MB + 2)
#define SMEM_BYTES (U_TOT * 8)         // 227,408 B (< 232,448 opt-in cap)

// W pre-paired: g_Wp[phase][kp][d] = {W(d,2kp), W(d,2kp+1)}; kp>=128 -> Wx cols; kp>=134 -> 0
__device__ float2 g_Wp[2][KPAD][D_];

__device__ __forceinline__ void ffma2(ull &d, ull a, ull b) {
    asm("fma.rn.f32x2 %0, %1, %2, %0;" : "+l"(d) : "l"(a), "l"(b));
}
__device__ __forceinline__ void unpack2(ull v, float &lo, float &hi) {
    asm("mov.b64 {%0, %1}, %2;" : "=f"(lo), "=f"(hi) : "l"(v));
}
__device__ __forceinline__ ull pk(float a, float b) {
    ull r; asm("mov.b64 %0, {%1, %2};" : "=l"(r) : "f"(a), "f"(b)); return r;
}
__device__ __forceinline__ float shflx(float v, int m) {
    float r;
    asm("shfl.sync.bfly.b32 %0, %1, %2, 0x1f, 0xffffffff;" : "=f"(r) : "f"(v), "r"(m));
    return r;
}
__device__ __forceinline__ unsigned smem_u32(const void* p) {
    unsigned r;
    asm("{ .reg .u64 t; cvta.to.shared.u64 t, %1; cvt.u32.u64 %0, t; }" : "=r"(r) : "l"(p));
    return r;
}
__device__ __forceinline__ void mbar_init(unsigned mb, unsigned cnt) {
    asm volatile("mbarrier.init.shared.b64 [%0], %1;" :: "r"(mb), "r"(cnt) : "memory");
}
__device__ __forceinline__ void mbar_wait(unsigned mb, unsigned parity) {
    unsigned done;
    asm volatile("{\n\t.reg .pred p;\n\t"
                 "mbarrier.try_wait.parity.acquire.cta.shared::cta.b64 p, [%1], %2;\n\t"
                 "selp.b32 %0, 1, 0, p;\n\t}"
                 : "=r"(done) : "r"(mb), "r"(parity) : "memory");
    if (!done) {
        asm volatile("{\n\t.reg .pred P;\n"
                     "W%=:\n\t"
                     "mbarrier.try_wait.parity.acquire.cta.shared::cta.b64 P, [%0], %1, 0x989680;\n\t"
                     "@P bra.uni D%=;\n\t"
                     "bra.uni W%=;\n"
                     "D%=:\n\t}"
                     :: "r"(mb), "r"(parity) : "memory");
    }
}
__device__ __forceinline__ void tma_issue(unsigned mb, unsigned dst, const void* src) {
    asm volatile("mbarrier.arrive.expect_tx.shared.b64 _, [%0], %1;"
                 :: "r"(mb), "r"((unsigned)CHBYTES) : "memory");
    asm volatile("cp.async.bulk.shared::cluster.global.mbarrier::complete_tx::bytes "
                 "[%0], [%1], %2, [%3];"
                 :: "r"(dst), "l"(src), "r"((unsigned)CHBYTES), "r"(mb) : "memory");
}
// one h value (duplicated k-pair for one row) times 8 outputs
__device__ __forceinline__ void row8(ull* a, ull h,
                                     const ulonglong2 &w0, const ulonglong2 &w1,
                                     const ulonglong2 &w2, const ulonglong2 &w3) {
    ffma2(a[0], h, w0.x); ffma2(a[1], h, w0.y);
    ffma2(a[2], h, w1.x); ffma2(a[3], h, w1.y);
    ffma2(a[4], h, w2.x); ffma2(a[5], h, w2.y);
    ffma2(a[6], h, w3.x); ffma2(a[7], h, w3.y);
}

// ---------------- prep: paired fused weight image ----------------
__global__ void prep_kernel(const float* __restrict__ eWh, const float* __restrict__ eWx,
                            const float* __restrict__ dWh, const float* __restrict__ dWx)
{
    int p  = blockIdx.x / KPAD;
    int kp = blockIdx.x % KPAD;
    int d  = threadIdx.x;
    const float* Wh = p ? dWh : eWh;
    const float* Wx = p ? dWx : eWx;
    int k0 = 2 * kp, k1 = 2 * kp + 1;
    float v0 = (k0 < D_) ? Wh[d * D_ + k0] : ((k0 < D_ + C_) ? Wx[d * C_ + (k0 - D_)] : 0.f);
    float v1 = (k1 < D_) ? Wh[d * D_ + k1] : ((k1 < D_ + C_) ? Wx[d * C_ + (k1 - D_)] : 0.f);
    g_Wp[p][kp][d] = make_float2(v0, v1);
}

// ---------------- main persistent kernel ----------------
extern "C" __global__ void __launch_bounds__(NTHR, 1)
seq2seq_kernel(const float* __restrict__ x,
               const float* __restrict__ ebx, const float* __restrict__ dbx,
               const float* __restrict__ dWy, const float* __restrict__ dby,
               float* __restrict__ out)
{
    extern __shared__ ull smu[];
    ull*   smW = smu + U_W;
    ull*   sh0 = smu + U_SH0;
    ull*   sh1 = smu + U_SH1;
    ull*   sWy = smu + U_WY;
    ull*   sbe = smu + U_BE;
    ull*   sbd = smu + U_BD;
    float* yt  = (float*)(smu + U_YT);
    float* sby = (float*)(smu + U_BY);

    const int tid  = threadIdx.x;
    const int lane = tid & 31;
    const int warp = tid >> 5;
    const int r0   = (tid & 3) * 8;       // 8 rows
    const int d0   = (tid >> 2) * 8;      // 8 outputs (ull index == output index)
    const int rowbase = blockIdx.x * RB;

    const unsigned sW_u32 = smem_u32(smu) + U_W * 8;
    const unsigned mb_u32 = smem_u32(smu) + U_MB * 8;

    const int c1 = tid >> 5;              // aug staging: pair-col (slot tid), row
    const int r1 = tid & 31;

    // ---- init ----
    for (int i = tid; i < 2 * HROWS * RB; i += NTHR) sh0[i] = 0ull;  // covers sh1+pads
    for (int i = tid; i < 12 * 128; i += NTHR) sWy[i] = ((const ull*)dWy)[i];
    for (int i = tid; i < D_; i += NTHR) {
        sbe[i] = pk(ebx[i], 0.f);
        sbd[i] = pk(dbx[i], 0.f);
    }
    if (tid < K_) sby[tid] = dby[tid];
    if (tid == 0) { mbar_init(mb_u32, 1); mbar_init(mb_u32 + 8, 1); }
    __syncthreads();

    // stage x_0 into buf0 aug rows (192 slots: tid, and tid+128 for tid<64)
    {
        const float2 a = *(const float2*)(x + ((size_t)rowbase + r1) * C_ + 2 * c1);
        sh0[(128 + c1) * RB + r1] = pk(a.x, a.y);
        if (tid < 64) {
            const float2 b = *(const float2*)(x + ((size_t)rowbase + r1) * C_ + 2 * (4 + c1));
            sh0[(132 + c1) * RB + r1] = pk(b.x, b.y);
        }
    }
    if (tid == 0) {   // prime chunks g=0 (buf0), g=1 (buf1), phase 0
        tma_issue(mb_u32,     sW_u32,           (const char*)g_Wp);
        tma_issue(mb_u32 + 8, sW_u32 + CHBYTES, (const char*)g_Wp + (size_t)CH * D_ * 8);
    }
    __syncthreads();

    ull acc[64];

    for (int t = 0; t < 2 * T_; ++t) {
        const bool dec = (t >= T_);
        ull* cur = (t & 1) ? sh1 : sh0;
        ull* nxt = (t & 1) ? sh0 : sh1;

        // prefetch next x slice into regs (encoder)
        ull xv1 = 0ull, xv2 = 0ull;
        if (!dec && (t + 1) < T_) {
            const float2 a = *(const float2*)(x + ((size_t)(t + 1) * N_ + rowbase + r1) * C_ + 2 * c1);
            xv1 = pk(a.x, a.y);
            if (tid < 64) {
                const float2 b = *(const float2*)(x + ((size_t)(t + 1) * N_ + rowbase + r1) * C_ + 2 * (4 + c1));
                xv2 = pk(b.x, b.y);
            }
        }

        // acc init = {bias, 0}
        {
            const ulonglong2* bp = (const ulonglong2*)((dec ? sbd : sbe) + d0);
            ulonglong2 b01 = bp[0], b23 = bp[1], b45 = bp[2], b67 = bp[3];
            ull bj[8] = {b01.x, b01.y, b23.x, b23.y, b45.x, b45.y, b67.x, b67.y};
            #pragma unroll
            for (int i = 0; i < 8; ++i)
                #pragma unroll
                for (int j = 0; j < 8; ++j) acc[i * 8 + j] = bj[j];
        }

        // ---- GEMM: 4 chunks of 34 kp; depth-1 LDS register pipeline ----
        #pragma unroll 1
        for (int c = 0; c < NCHK; ++c) {
            const int g   = t * NCHK + c;
            const int b   = g & 1;
            const unsigned par = (unsigned)((g >> 1) & 1);
            mbar_wait(mb_u32 + b * 8, par);

            const ulonglong2* wq = (const ulonglong2*)(smW + (size_t)b * CHW + d0);
            const ulonglong2* hq = (const ulonglong2*)(cur + (size_t)(c * CH) * RB + r0);

            // prime kp0 into A
            ulonglong2 wA0 = wq[0], wA1 = wq[1], wA2 = wq[2], wA3 = wq[3];
            ulonglong2 hA0 = hq[0], hA1 = hq[1], hA2 = hq[2], hA3 = hq[3];

            #pragma unroll 2
            for (int kk = 0; kk < CH; kk += 2) {
                // load kp kk+1 into B
                wq += 128; hq += 16;
                ulonglong2 wB0 = wq[0], wB1 = wq[1], wB2 = wq[2], wB3 = wq[3];
                ulonglong2 hB0 = hq[0], hB1 = hq[1], hB2 = hq[2], hB3 = hq[3];

                // compute kp kk (A)
                row8(acc + 0,  hA0.x, wA0, wA1, wA2, wA3);
                row8(acc + 8,  hA0.y, wA0, wA1, wA2, wA3);
                row8(acc + 16, hA1.x, wA0, wA1, wA2, wA3);
                row8(acc + 24, hA1.y, wA0, wA1, wA2, wA3);
                row8(acc + 32, hA2.x, wA0, wA1, wA2, wA3);
                row8(acc + 40, hA2.y, wA0, wA1, wA2, wA3);
                row8(acc + 48, hA3.x, wA0, wA1, wA2, wA3);
                row8(acc + 56, hA3.y, wA0, wA1, wA2, wA3);

                // load kp kk+2 into A (over-read at chunk end -> pad row / adjacent smem)
                wq += 128; hq += 16;
                wA0 = wq[0]; wA1 = wq[1]; wA2 = wq[2]; wA3 = wq[3];
                hA0 = hq[0]; hA1 = hq[1]; hA2 = hq[2]; hA3 = hq[3];

                // compute kp kk+1 (B)
                row8(acc + 0,  hB0.x, wB0, wB1, wB2, wB3);
                row8(acc + 8,  hB0.y, wB0, wB1, wB2, wB3);
                row8(acc + 16, hB1.x, wB0, wB1, wB2, wB3);
                row8(acc + 24, hB1.y, wB0, wB1, wB2, wB3);
                row8(acc + 32, hB2.x, wB0, wB1, wB2, wB3);
                row8(acc + 40, hB2.y, wB0, wB1, wB2, wB3);
                row8(acc + 48, hB3.x, wB0, wB1, wB2, wB3);
                row8(acc + 56, hB3.y, wB0, wB1, wB2, wB3);
            }
            __syncthreads();   // buffer b consumed by all threads

            if (tid == 0 && (g + 2) < GTOT) {
                const int g2 = g + 2;
                const int t2 = g2 >> 2, c2 = g2 & 3;
                const int ph = (t2 >= T_) ? 1 : 0;
                tma_issue(mb_u32 + b * 8, sW_u32 + b * CHBYTES,
                          (const char*)g_Wp + ((size_t)ph * KPAD + c2 * CH) * D_ * 8);
            }
        }

        // ---- epilogue: h = relu(lo+hi), store paired h into NXT ----
        #pragma unroll
        for (int j2 = 0; j2 < 4; ++j2) {
            float4* dst = (float4*)(nxt + (size_t)((d0 >> 1) + j2) * RB + r0);
            #pragma unroll
            for (int i2 = 0; i2 < 4; ++i2) {   // rows 2*i2, 2*i2+1
                float a0, b0, a1, b1, a2, b2, a3, b3;
                unpack2(acc[(2 * i2) * 8 + 2 * j2],         a0, b0);
                unpack2(acc[(2 * i2) * 8 + 2 * j2 + 1],     a1, b1);
                unpack2(acc[(2 * i2 + 1) * 8 + 2 * j2],     a2, b2);
                unpack2(acc[(2 * i2 + 1) * 8 + 2 * j2 + 1], a3, b3);
                dst[i2] = make_float4(fmaxf(a0 + b0, 0.f), fmaxf(a1 + b1, 0.f),
                                      fmaxf(a2 + b2, 0.f), fmaxf(a3 + b3, 0.f));
            }
        }
        if (!dec) {   // stage x_{t+1} or SOS (col 10 -> pair 5 = {1,0}) into NXT aug
            if (t + 1 < T_) {
                nxt[(128 + c1) * RB + r1] = xv1;
                if (tid < 64) nxt[(132 + c1) * RB + r1] = xv2;
            } else {
                nxt[(128 + c1) * RB + r1] = 0ull;
                if (tid < 64) nxt[(132 + c1) * RB + r1] = (c1 == 1) ? pk(1.f, 0.f) : 0ull;
            }
        }
        __syncthreads();   // publish new h (+aug)

        // ---- decoder: tiled y = h @ Wy^T + by (4 warps), argmax, feedback ----
        if (dec) {
            const int kg = lane & 3;          // k in {kg, kg+4, kg+8}
            const int mg = lane >> 2;         // m-chunk [16*mg, 16*mg+16)
            const int rw = warp * 8;          // 8 rows per warp
            const ull* w0 = sWy + kg * 128;
            const ull* w1 = sWy + (kg + 4) * 128;
            const ull* w2 = sWy + (kg + 8) * 128;
            ull a[24];                         // [row 8][k 3]
            #pragma unroll
            for (int q = 0; q < 24; ++q) a[q] = 0ull;
            const int mbase = mg * 16;
            #pragma unroll 4
            for (int mm = 0; mm < 16; ++mm) {
                const int m = mbase + mm;
                const ulonglong2* hp = (const ulonglong2*)(nxt + (size_t)m * RB + rw);
                ulonglong2 h01 = hp[0], h23 = hp[1], h45 = hp[2], h67 = hp[3];
                ull hr[8] = {h01.x, h01.y, h23.x, h23.y, h45.x, h45.y, h67.x, h67.y};
                ull wv0 = w0[m], wv1 = w1[m], wv2 = w2[m];
                #pragma unroll
                for (int i = 0; i < 8; ++i) {
                    ffma2(a[i * 3 + 0], hr[i], wv0);
                    ffma2(a[i * 3 + 1], hr[i], wv1);
                    ffma2(a[i * 3 + 2], hr[i], wv2);
                }
            }
            float v[24];
            #pragma unroll
            for (int q = 0; q < 24; ++q) {
                float lo, hi; unpack2(a[q], lo, hi);
                v[q] = lo + hi;
            }
            #pragma unroll
            for (int q = 0; q < 24; ++q) {
                v[q] += shflx(v[q], 4);
                v[q] += shflx(v[q], 8);
                v[q] += shflx(v[q], 16);
            }
            if (mg == 0) {
                #pragma unroll
                for (int i = 0; i < 8; ++i) {
                    yt[(rw + i) * 12 + kg]     = v[i * 3 + 0] + sby[kg];
                    yt[(rw + i) * 12 + kg + 4] = v[i * 3 + 1] + sby[kg + 4];
                    yt[(rw + i) * 12 + kg + 8] = v[i * 3 + 2] + sby[kg + 8];
                }
            }
            __syncthreads();   // yt complete
            if (tid < 32) {
                const float* yr = yt + tid * 12;
                float vv[12];
                #pragma unroll
                for (int q = 0; q < 3; ++q) {
                    float4 fv = *(const float4*)(yr + 4 * q);
                    vv[4 * q] = fv.x; vv[4 * q + 1] = fv.y;
                    vv[4 * q + 2] = fv.z; vv[4 * q + 3] = fv.w;
                }
                float best = vv[0]; int sel = 0;
                #pragma unroll
                for (int q = 1; q < 12; ++q)
                    if (vv[q] > best) { best = vv[q]; sel = q; }   // first-max wins
                float* og = out + ((size_t)(t - T_) * N_ + rowbase + tid) * K_;
                *(float4*)(og)     = make_float4(vv[0], vv[1], vv[2],  vv[3]);
                *(float4*)(og + 4) = make_float4(vv[4], vv[5], vv[6],  vv[7]);
                *(float4*)(og + 8) = make_float4(vv[8], vv[9], vv[10], vv[11]);
                // NXT aug: zero all 6 pair-cols for this row, set one-hot.
                // Visible to next step's chunk-3 reads via 3 intervening chunk barriers.
                const ull oh = (sel & 1) ? pk(0.f, 1.f) : pk(1.f, 0.f);
                #pragma unroll
                for (int cc = 0; cc < 6; ++cc)
                    nxt[(128 + cc) * RB + tid] = (cc == (sel >> 1)) ? oh : 0ull;
            }
            // no trailing barrier: warp0 joins chunk-0 barrier of next step
        }
    }
}

extern "C" void kernel_launch(void* const* d_in, const int* in_sizes, int n_in,
                              void* d_out, int out_size) {
    const float* x   = (const float*)d_in[0];
    const float* eWx = (const float*)d_in[1];
    const float* ebx = (const float*)d_in[2];
    const float* eWh = (const float*)d_in[3];
    const float* dWx = (const float*)d_in[6];
    const float* dbx = (const float*)d_in[7];
    const float* dWh = (const float*)d_in[8];
    const float* dWy = (const float*)d_in[9];
    const float* dby = (const float*)d_in[10];

    prep_kernel<<<2 * KPAD, D_>>>(eWh, eWx, dWh, dWx);

    cudaFuncSetAttribute(seq2seq_kernel,
                         cudaFuncAttributeMaxDynamicSharedMemorySize, SMEM_BYTES);
    seq2seq_kernel<<<NBLK, NTHR, SMEM_BYTES>>>(
        x, ebx, dbx, dWy, dby, (float*)d_out);
}

// round 13
// speedup vs baseline: 1.1821x; 1.0017x over previous
#include <cuda_runtime.h>
#include <cstdint>

#define T_    256
#define N_    4096
#define C_    12
#define D_    256
#define K_    12
#define KPAD  136          // 272/2 k-pairs: 128 h + 6 x/onehot + 2 zero pad
#define RB    32
#define NTHR  128
#define NBLK  (N_ / RB)    // 128
#define CH    34           // k-pairs per TMA chunk; 4 chunks = 136
#define NCHK  4
#define CHW   (CH * D_)    // ull per chunk (8704)
#define CHBYTES (CHW * 8)  // 69632
#define GTOT  (2 * T_ * NCHK)   // 2048
#define HROWS (KPAD + 1)   // 1 pad row absorbs pipeline over-read

typedef unsigned long long ull;

// ---- smem layout (ull units) ----
#define U_W    0                       // 2 chunk buffers: 17408
#define U_SH0  (U_W + 2 * CHW)         // h_aug buf0 [137][32]
#define U_SH1  (U_SH0 + HROWS * RB)    // h_aug buf1
#define U_WY   (U_SH1 + HROWS * RB)    // Wy paired [12][128]
#define U_BE   (U_WY + 12 * 128)       // enc bias {b,0} [256]
#define U_BD   (U_BE + 256)            // dec bias {b,0} [256]
#define U_YT   (U_BD + 256)            // ytmp 384 floats = 192 ull
#define U_BY   (U_YT + 192)            // by 12 floats (pad 16)
#define U_MB   (U_BY + 8)              // 2 mbarriers
#define U_TOT  (U_MB + 2)
#define SMEM_BYTES (U_TOT * 8)         // 227,408 B (< 232,448 opt-in cap)

// W pre-paired: g_Wp[phase][kp][d] = {W(d,2kp), W(d,2kp+1)}; kp>=128 -> Wx cols; kp>=134 -> 0
__device__ float2 g_Wp[2][KPAD][D_];

__device__ __forceinline__ void ffma2(ull &d, ull a, ull b) {
    asm("fma.rn.f32x2 %0, %1, %2, %0;" : "+l"(d) : "l"(a), "l"(b));
}
__device__ __forceinline__ void unpack2(ull v, float &lo, float &hi) {
    asm("mov.b64 {%0, %1}, %2;" : "=f"(lo), "=f"(hi) : "l"(v));
}
__device__ __forceinline__ ull pk(float a, float b) {
    ull r; asm("mov.b64 %0, {%1, %2};" : "=l"(r) : "f"(a), "f"(b)); return r;
}
__device__ __forceinline__ float shflx(float v, int m) {
    float r;
    asm("shfl.sync.bfly.b32 %0, %1, %2, 0x1f, 0xffffffff;" : "=f"(r) : "f"(v), "r"(m));
    return r;
}
__device__ __forceinline__ unsigned smem_u32(const void* p) {
    unsigned r;
    asm("{ .reg .u64 t; cvta.to.shared.u64 t, %1; cvt.u32.u64 %0, t; }" : "=r"(r) : "l"(p));
    return r;
}
__device__ __forceinline__ void mbar_init(unsigned mb, unsigned cnt) {
    asm volatile("mbarrier.init.shared.b64 [%0], %1;" :: "r"(mb), "r"(cnt) : "memory");
}
__device__ __forceinline__ void mbar_wait(unsigned mb, unsigned parity) {
    unsigned done;
    asm volatile("{\n\t.reg .pred p;\n\t"
                 "mbarrier.try_wait.parity.acquire.cta.shared::cta.b64 p, [%1], %2;\n\t"
                 "selp.b32 %0, 1, 0, p;\n\t}"
                 : "=r"(done) : "r"(mb), "r"(parity) : "memory");
    if (!done) {
        asm volatile("{\n\t.reg .pred P;\n"
                     "W%=:\n\t"
                     "mbarrier.try_wait.parity.acquire.cta.shared::cta.b64 P, [%0], %1, 0x989680;\n\t"
                     "@P bra.uni D%=;\n\t"
                     "bra.uni W%=;\n"
                     "D%=:\n\t}"
                     :: "r"(mb), "r"(parity) : "memory");
    }
}
__device__ __forceinline__ void tma_issue(unsigned mb, unsigned dst, const void* src) {
    asm volatile("mbarrier.arrive.expect_tx.shared.b64 _, [%0], %1;"
                 :: "r"(mb), "r"((unsigned)CHBYTES) : "memory");
    asm volatile("cp.async.bulk.shared::cluster.global.mbarrier::complete_tx::bytes "
                 "[%0], [%1], %2, [%3];"
                 :: "r"(dst), "l"(src), "r"((unsigned)CHBYTES), "r"(mb) : "memory");
}
// one h value (duplicated k-pair for one row) times 8 outputs
__device__ __forceinline__ void row8(ull* a, ull h,
                                     const ulonglong2 &w0, const ulonglong2 &w1,
                                     const ulonglong2 &w2, const ulonglong2 &w3) {
    ffma2(a[0], h, w0.x); ffma2(a[1], h, w0.y);
    ffma2(a[2], h, w1.x); ffma2(a[3], h, w1.y);
    ffma2(a[4], h, w2.x); ffma2(a[5], h, w2.y);
    ffma2(a[6], h, w3.x); ffma2(a[7], h, w3.y);
}

// ---------------- prep: paired fused weight image ----------------
__global__ void prep_kernel(const float* __restrict__ eWh, const float* __restrict__ eWx,
                            const float* __restrict__ dWh, const float* __restrict__ dWx)
{
    int p  = blockIdx.x / KPAD;
    int kp = blockIdx.x % KPAD;
    int d  = threadIdx.x;
    const float* Wh = p ? dWh : eWh;
    const float* Wx = p ? dWx : eWx;
    int k0 = 2 * kp, k1 = 2 * kp + 1;
    float v0 = (k0 < D_) ? Wh[d * D_ + k0] : ((k0 < D_ + C_) ? Wx[d * C_ + (k0 - D_)] : 0.f);
    float v1 = (k1 < D_) ? Wh[d * D_ + k1] : ((k1 < D_ + C_) ? Wx[d * C_ + (k1 - D_)] : 0.f);
    g_Wp[p][kp][d] = make_float2(v0, v1);
}

// ---------------- main persistent kernel ----------------
extern "C" __global__ void __launch_bounds__(NTHR, 1)
seq2seq_kernel(const float* __restrict__ x,
               const float* __restrict__ ebx, const float* __restrict__ dbx,
               const float* __restrict__ dWy, const float* __restrict__ dby,
               float* __restrict__ out)
{
    extern __shared__ ull smu[];
    ull*   smW = smu + U_W;
    ull*   sh0 = smu + U_SH0;
    ull*   sh1 = smu + U_SH1;
    ull*   sWy = smu + U_WY;
    ull*   sbe = smu + U_BE;
    ull*   sbd = smu + U_BD;
    float* yt  = (float*)(smu + U_YT);
    float* sby = (float*)(smu + U_BY);

    const int tid  = threadIdx.x;
    const int lane = tid & 31;
    const int warp = tid >> 5;
    const int r0   = (tid & 3) * 8;       // 8 rows
    const int d0   = (tid >> 2) * 8;      // 8 outputs (ull index == output index)
    const int rowbase = blockIdx.x * RB;

    const unsigned sW_u32 = smem_u32(smu) + U_W * 8;
    const unsigned mb_u32 = smem_u32(smu) + U_MB * 8;

    const int c1 = tid >> 5;              // aug staging: pair-col (slot tid), row
    const int r1 = tid & 31;

    // ---- init ----
    for (int i = tid; i < 2 * HROWS * RB; i += NTHR) sh0[i] = 0ull;  // covers sh1+pads
    for (int i = tid; i < 12 * 128; i += NTHR) sWy[i] = ((const ull*)dWy)[i];
    for (int i = tid; i < D_; i += NTHR) {
        sbe[i] = pk(ebx[i], 0.f);
        sbd[i] = pk(dbx[i], 0.f);
    }
    if (tid < K_) sby[tid] = dby[tid];
    if (tid == 0) { mbar_init(mb_u32, 1); mbar_init(mb_u32 + 8, 1); }
    __syncthreads();

    // stage x_0 into buf0 aug rows (192 slots: tid, and tid+128 for tid<64)
    {
        const float2 a = *(const float2*)(x + ((size_t)rowbase + r1) * C_ + 2 * c1);
        sh0[(128 + c1) * RB + r1] = pk(a.x, a.y);
        if (tid < 64) {
            const float2 b = *(const float2*)(x + ((size_t)rowbase + r1) * C_ + 2 * (4 + c1));
            sh0[(132 + c1) * RB + r1] = pk(b.x, b.y);
        }
    }
    if (tid == 0) {   // prime chunks g=0 (buf0), g=1 (buf1), phase 0
        tma_issue(mb_u32,     sW_u32,           (const char*)g_Wp);
        tma_issue(mb_u32 + 8, sW_u32 + CHBYTES, (const char*)g_Wp + (size_t)CH * D_ * 8);
    }
    __syncthreads();

    ull acc[64];

    for (int t = 0; t < 2 * T_; ++t) {
        const bool dec = (t >= T_);
        ull* cur = (t & 1) ? sh1 : sh0;
        ull* nxt = (t & 1) ? sh0 : sh1;

        // prefetch next x slice into regs (encoder)
        ull xv1 = 0ull, xv2 = 0ull;
        if (!dec && (t + 1) < T_) {
            const float2 a = *(const float2*)(x + ((size_t)(t + 1) * N_ + rowbase + r1) * C_ + 2 * c1);
            xv1 = pk(a.x, a.y);
            if (tid < 64) {
                const float2 b = *(const float2*)(x + ((size_t)(t + 1) * N_ + rowbase + r1) * C_ + 2 * (4 + c1));
                xv2 = pk(b.x, b.y);
            }
        }

        // acc init = {bias, 0}
        {
            const ulonglong2* bp = (const ulonglong2*)((dec ? sbd : sbe) + d0);
            ulonglong2 b01 = bp[0], b23 = bp[1], b45 = bp[2], b67 = bp[3];
            ull bj[8] = {b01.x, b01.y, b23.x, b23.y, b45.x, b45.y, b67.x, b67.y};
            #pragma unroll
            for (int i = 0; i < 8; ++i)
                #pragma unroll
                for (int j = 0; j < 8; ++j) acc[i * 8 + j] = bj[j];
        }

        // ---- GEMM: 4 chunks of 34 kp; depth-1 LDS register pipeline ----
        #pragma unroll 1
        for (int c = 0; c < NCHK; ++c) {
            const int g   = t * NCHK + c;
            const int b   = g & 1;
            const unsigned par = (unsigned)((g >> 1) & 1);
            mbar_wait(mb_u32 + b * 8, par);

            const ulonglong2* wq = (const ulonglong2*)(smW + (size_t)b * CHW + d0);
            const ulonglong2* hq = (const ulonglong2*)(cur + (size_t)(c * CH) * RB + r0);

            // prime kp0 into A
            ulonglong2 wA0 = wq[0], wA1 = wq[1], wA2 = wq[2], wA3 = wq[3];
            ulonglong2 hA0 = hq[0], hA1 = hq[1], hA2 = hq[2], hA3 = hq[3];

            #pragma unroll 2
            for (int kk = 0; kk < CH; kk += 2) {
                // load kp kk+1 into B
                wq += 128; hq += 16;
                ulonglong2 wB0 = wq[0], wB1 = wq[1], wB2 = wq[2], wB3 = wq[3];
                ulonglong2 hB0 = hq[0], hB1 = hq[1], hB2 = hq[2], hB3 = hq[3];

                // compute kp kk (A)
                row8(acc + 0,  hA0.x, wA0, wA1, wA2, wA3);
                row8(acc + 8,  hA0.y, wA0, wA1, wA2, wA3);
                row8(acc + 16, hA1.x, wA0, wA1, wA2, wA3);
                row8(acc + 24, hA1.y, wA0, wA1, wA2, wA3);
                row8(acc + 32, hA2.x, wA0, wA1, wA2, wA3);
                row8(acc + 40, hA2.y, wA0, wA1, wA2, wA3);
                row8(acc + 48, hA3.x, wA0, wA1, wA2, wA3);
                row8(acc + 56, hA3.y, wA0, wA1, wA2, wA3);

                // load kp kk+2 into A (over-read at chunk end -> pad row / adjacent smem)
                wq += 128; hq += 16;
                wA0 = wq[0]; wA1 = wq[1]; wA2 = wq[2]; wA3 = wq[3];
                hA0 = hq[0]; hA1 = hq[1]; hA2 = hq[2]; hA3 = hq[3];

                // compute kp kk+1 (B)
                row8(acc + 0,  hB0.x, wB0, wB1, wB2, wB3);
                row8(acc + 8,  hB0.y, wB0, wB1, wB2, wB3);
                row8(acc + 16, hB1.x, wB0, wB1, wB2, wB3);
                row8(acc + 24, hB1.y, wB0, wB1, wB2, wB3);
                row8(acc + 32, hB2.x, wB0, wB1, wB2, wB3);
                row8(acc + 40, hB2.y, wB0, wB1, wB2, wB3);
                row8(acc + 48, hB3.x, wB0, wB1, wB2, wB3);
                row8(acc + 56, hB3.y, wB0, wB1, wB2, wB3);
            }
            __syncthreads();   // buffer b consumed by all threads

            if (tid == 0 && (g + 2) < GTOT) {
                const int g2 = g + 2;
                const int t2 = g2 >> 2, c2 = g2 & 3;
                const int ph = (t2 >= T_) ? 1 : 0;
                tma_issue(mb_u32 + b * 8, sW_u32 + b * CHBYTES,
                          (const char*)g_Wp + ((size_t)ph * KPAD + c2 * CH) * D_ * 8);
            }
        }

        // ---- epilogue: h = relu(lo+hi), store paired h into NXT ----
        #pragma unroll
        for (int j2 = 0; j2 < 4; ++j2) {
            float4* dst = (float4*)(nxt + (size_t)((d0 >> 1) + j2) * RB + r0);
            #pragma unroll
            for (int i2 = 0; i2 < 4; ++i2) {   // rows 2*i2, 2*i2+1
                float a0, b0, a1, b1, a2, b2, a3, b3;
                unpack2(acc[(2 * i2) * 8 + 2 * j2],         a0, b0);
                unpack2(acc[(2 * i2) * 8 + 2 * j2 + 1],     a1, b1);
                unpack2(acc[(2 * i2 + 1) * 8 + 2 * j2],     a2, b2);
                unpack2(acc[(2 * i2 + 1) * 8 + 2 * j2 + 1], a3, b3);
                dst[i2] = make_float4(fmaxf(a0 + b0, 0.f), fmaxf(a1 + b1, 0.f),
                                      fmaxf(a2 + b2, 0.f), fmaxf(a3 + b3, 0.f));
            }
        }
        if (!dec) {   // stage x_{t+1} or SOS (col 10 -> pair 5 = {1,0}) into NXT aug
            if (t + 1 < T_) {
                nxt[(128 + c1) * RB + r1] = xv1;
                if (tid < 64) nxt[(132 + c1) * RB + r1] = xv2;
            } else {
                nxt[(128 + c1) * RB + r1] = 0ull;
                if (tid < 64) nxt[(132 + c1) * RB + r1] = (c1 == 1) ? pk(1.f, 0.f) : 0ull;
            }
        }
        __syncthreads();   // publish new h (+aug)

        // ---- decoder: tiled y = h @ Wy^T + by (4 warps), argmax, feedback ----
        if (dec) {
            const int kg = lane & 3;          // k in {kg, kg+4, kg+8}
            const int mg = lane >> 2;         // m-chunk [16*mg, 16*mg+16)
            const int rw = warp * 8;          // 8 rows per warp
            const ull* w0 = sWy + kg * 128;
            const ull* w1 = sWy + (kg + 4) * 128;
            const ull* w2 = sWy + (kg + 8) * 128;
            ull a[24];                         // [row 8][k 3]
            #pragma unroll
            for (int q = 0; q < 24; ++q) a[q] = 0ull;
            const int mbase = mg * 16;
            #pragma unroll 4
            for (int mm = 0; mm < 16; ++mm) {
                const int m = mbase + mm;
                const ulonglong2* hp = (const ulonglong2*)(nxt + (size_t)m * RB + rw);
                ulonglong2 h01 = hp[0], h23 = hp[1], h45 = hp[2], h67 = hp[3];
                ull hr[8] = {h01.x, h01.y, h23.x, h23.y, h45.x, h45.y, h67.x, h67.y};
                ull wv0 = w0[m], wv1 = w1[m], wv2 = w2[m];
                #pragma unroll
                for (int i = 0; i < 8; ++i) {
                    ffma2(a[i * 3 + 0], hr[i], wv0);
                    ffma2(a[i * 3 + 1], hr[i], wv1);
                    ffma2(a[i * 3 + 2], hr[i], wv2);
                }
            }
            float v[24];
            #pragma unroll
            for (int q = 0; q < 24; ++q) {
                float lo, hi; unpack2(a[q], lo, hi);
                v[q] = lo + hi;
            }
            #pragma unroll
            for (int q = 0; q < 24; ++q) {
                v[q] += shflx(v[q], 4);
                v[q] += shflx(v[q], 8);
                v[q] += shflx(v[q], 16);
            }
            if (mg == 0) {
                #pragma unroll
                for (int i = 0; i < 8; ++i) {
                    yt[(rw + i) * 12 + kg]     = v[i * 3 + 0] + sby[kg];
                    yt[(rw + i) * 12 + kg + 4] = v[i * 3 + 1] + sby[kg + 4];
                    yt[(rw + i) * 12 + kg + 8] = v[i * 3 + 2] + sby[kg + 8];
                }
            }
            __syncthreads();   // yt complete
            if (tid < 32) {
                const float* yr = yt + tid * 12;
                float vv[12];
                #pragma unroll
                for (int q = 0; q < 3; ++q) {
                    float4 fv = *(const float4*)(yr + 4 * q);
                    vv[4 * q] = fv.x; vv[4 * q + 1] = fv.y;
                    vv[4 * q + 2] = fv.z; vv[4 * q + 3] = fv.w;
                }
                float best = vv[0]; int sel = 0;
                #pragma unroll
                for (int q = 1; q < 12; ++q)
                    if (vv[q] > best) { best = vv[q]; sel = q; }   // first-max wins
                float* og = out + ((size_t)(t - T_) * N_ + rowbase + tid) * K_;
                *(float4*)(og)     = make_float4(vv[0], vv[1], vv[2],  vv[3]);
                *(float4*)(og + 4) = make_float4(vv[4], vv[5], vv[6],  vv[7]);
                *(float4*)(og + 8) = make_float4(vv[8], vv[9], vv[10], vv[11]);
                // NXT aug: zero all 6 pair-cols for this row, set one-hot.
                // Visible to next step's chunk-3 reads via 3 intervening chunk barriers.
                const ull oh = (sel & 1) ? pk(0.f, 1.f) : pk(1.f, 0.f);
                #pragma unroll
                for (int cc = 0; cc < 6; ++cc)
                    nxt[(128 + cc) * RB + tid] = (cc == (sel >> 1)) ? oh : 0ull;
            }
            // no trailing barrier: warp0 joins chunk-0 barrier of next step
        }
    }
}

extern "C" void kernel_launch(void* const* d_in, const int* in_sizes, int n_in,
                              void* d_out, int out_size) {
    const float* x   = (const float*)d_in[0];
    const float* eWx = (const float*)d_in[1];
    const float* ebx = (const float*)d_in[2];
    const float* eWh = (const float*)d_in[3];
    const float* dWx = (const float*)d_in[6];
    const float* dbx = (const float*)d_in[7];
    const float* dWh = (const float*)d_in[8];
    const float* dWy = (const float*)d_in[9];
    const float* dby = (const float*)d_in[10];

    prep_kernel<<<2 * KPAD, D_>>>(eWh, eWx, dWh, dWx);

    cudaFuncSetAttribute(seq2seq_kernel,
                         cudaFuncAttributeMaxDynamicSharedMemorySize, SMEM_BYTES);
    seq2seq_kernel<<<NBLK, NTHR, SMEM_BYTES>>>(
        x, ebx, dbx, dWy, dby, (float*)d_out);
}

// round 14
// speedup vs baseline: 1.1839x; 1.0015x over previous
#include <cuda_runtime.h>
#include <cstdint>

#define T_    256
#define N_    4096
#define C_    12
#define D_    256
#define K_    12
#define KPAD  136          // 272/2 k-pairs: 128 h + 6 x/onehot + 2 zero pad
#define RB    32
#define NTHR  128
#define NBLK  (N_ / RB)    // 128
#define CH    34           // k-pairs per TMA chunk; 4 chunks = 136
#define NCHK  4
#define CHW   (CH * D_)    // ull per chunk (8704)
#define CHBYTES (CHW * 8)  // 69632
#define GTOT  (2 * T_ * NCHK)   // 2048
#define HROWS (KPAD + 1)   // 1 pad row absorbs pipeline over-read

typedef unsigned long long ull;

// ---- smem layout (ull units) ----
#define U_W    0                       // 2 chunk buffers: 17408
#define U_SH0  (U_W + 2 * CHW)         // h_aug buf0 [137][32]
#define U_SH1  (U_SH0 + HROWS * RB)    // h_aug buf1
#define U_WY   (U_SH1 + HROWS * RB)    // Wy paired [12][128]
#define U_BE   (U_WY + 12 * 128)       // enc bias {b,0} [256]
#define U_BD   (U_BE + 256)            // dec bias {b,0} [256]
#define U_YT   (U_BD + 256)            // ytmp 384 floats = 192 ull
#define U_BY   (U_YT + 192)            // by 12 floats (pad 16)
#define U_MB   (U_BY + 8)              // 2 mbarriers
#define U_TOT  (U_MB + 2)
#define SMEM_BYTES (U_TOT * 8)         // 227,408 B (< 232,448 opt-in cap)

// W pre-paired: g_Wp[phase][kp][d] = {W(d,2kp), W(d,2kp+1)}; kp>=128 -> Wx cols; kp>=134 -> 0
__device__ float2 g_Wp[2][KPAD][D_];

__device__ __forceinline__ void ffma2(ull &d, ull a, ull b) {
    asm("fma.rn.f32x2 %0, %1, %2, %0;" : "+l"(d) : "l"(a), "l"(b));
}
__device__ __forceinline__ void unpack2(ull v, float &lo, float &hi) {
    asm("mov.b64 {%0, %1}, %2;" : "=f"(lo), "=f"(hi) : "l"(v));
}
__device__ __forceinline__ ull pk(float a, float b) {
    ull r; asm("mov.b64 %0, {%1, %2};" : "=l"(r) : "f"(a), "f"(b)); return r;
}
__device__ __forceinline__ float shflx(float v, int m) {
    float r;
    asm("shfl.sync.bfly.b32 %0, %1, %2, 0x1f, 0xffffffff;" : "=f"(r) : "f"(v), "r"(m));
    return r;
}
__device__ __forceinline__ unsigned smem_u32(const void* p) {
    unsigned r;
    asm("{ .reg .u64 t; cvta.to.shared.u64 t, %1; cvt.u32.u64 %0, t; }" : "=r"(r) : "l"(p));
    return r;
}
__device__ __forceinline__ void mbar_init(unsigned mb, unsigned cnt) {
    asm volatile("mbarrier.init.shared.b64 [%0], %1;" :: "r"(mb), "r"(cnt) : "memory");
}
__device__ __forceinline__ void mbar_wait(unsigned mb, unsigned parity) {
    unsigned done;
    asm volatile("{\n\t.reg .pred p;\n\t"
                 "mbarrier.try_wait.parity.acquire.cta.shared::cta.b64 p, [%1], %2;\n\t"
                 "selp.b32 %0, 1, 0, p;\n\t}"
                 : "=r"(done) : "r"(mb), "r"(parity) : "memory");
    if (!done) {
        asm volatile("{\n\t.reg .pred P;\n"
                     "W%=:\n\t"
                     "mbarrier.try_wait.parity.acquire.cta.shared::cta.b64 P, [%0], %1, 0x989680;\n\t"
                     "@P bra.uni D%=;\n\t"
                     "bra.uni W%=;\n"
                     "D%=:\n\t}"
                     :: "r"(mb), "r"(parity) : "memory");
    }
}
__device__ __forceinline__ void tma_issue(unsigned mb, unsigned dst, const void* src) {
    asm volatile("mbarrier.arrive.expect_tx.shared.b64 _, [%0], %1;"
                 :: "r"(mb), "r"((unsigned)CHBYTES) : "memory");
    asm volatile("cp.async.bulk.shared::cluster.global.mbarrier::complete_tx::bytes "
                 "[%0], [%1], %2, [%3];"
                 :: "r"(dst), "l"(src), "r"((unsigned)CHBYTES), "r"(mb) : "memory");
}
// one h value (duplicated k-pair for one row) times 8 outputs
__device__ __forceinline__ void row8(ull* a, ull h,
                                     const ulonglong2 &w0, const ulonglong2 &w1,
                                     const ulonglong2 &w2, const ulonglong2 &w3) {
    ffma2(a[0], h, w0.x); ffma2(a[1], h, w0.y);
    ffma2(a[2], h, w1.x); ffma2(a[3], h, w1.y);
    ffma2(a[4], h, w2.x); ffma2(a[5], h, w2.y);
    ffma2(a[6], h, w3.x); ffma2(a[7], h, w3.y);
}

// ---------------- prep: paired fused weight image ----------------
__global__ void prep_kernel(const float* __restrict__ eWh, const float* __restrict__ eWx,
                            const float* __restrict__ dWh, const float* __restrict__ dWx)
{
    int p  = blockIdx.x / KPAD;
    int kp = blockIdx.x % KPAD;
    int d  = threadIdx.x;
    const float* Wh = p ? dWh : eWh;
    const float* Wx = p ? dWx : eWx;
    int k0 = 2 * kp, k1 = 2 * kp + 1;
    float v0 = (k0 < D_) ? Wh[d * D_ + k0] : ((k0 < D_ + C_) ? Wx[d * C_ + (k0 - D_)] : 0.f);
    float v1 = (k1 < D_) ? Wh[d * D_ + k1] : ((k1 < D_ + C_) ? Wx[d * C_ + (k1 - D_)] : 0.f);
    g_Wp[p][kp][d] = make_float2(v0, v1);
}

// ---------------- main persistent kernel ----------------
extern "C" __global__ void __launch_bounds__(NTHR, 1)
seq2seq_kernel(const float* __restrict__ x,
               const float* __restrict__ ebx, const float* __restrict__ dbx,
               const float* __restrict__ dWy, const float* __restrict__ dby,
               float* __restrict__ out)
{
    extern __shared__ ull smu[];
    ull*   smW = smu + U_W;
    ull*   sh0 = smu + U_SH0;
    ull*   sh1 = smu + U_SH1;
    ull*   sWy = smu + U_WY;
    ull*   sbe = smu + U_BE;
    ull*   sbd = smu + U_BD;
    float* yt  = (float*)(smu + U_YT);
    float* sby = (float*)(smu + U_BY);

    const int tid  = threadIdx.x;
    const int lane = tid & 31;
    const int warp = tid >> 5;
    const int r0   = (tid & 3) * 8;       // 8 rows
    const int d0   = (tid >> 2) * 8;      // 8 outputs (ull index == output index)
    const int rowbase = blockIdx.x * RB;

    const unsigned sW_u32 = smem_u32(smu) + U_W * 8;
    const unsigned mb_u32 = smem_u32(smu) + U_MB * 8;

    const int c1 = tid >> 5;              // aug staging: pair-col (slot tid), row
    const int r1 = tid & 31;

    // ---- init ----
    for (int i = tid; i < 2 * HROWS * RB; i += NTHR) sh0[i] = 0ull;  // covers sh1+pads
    for (int i = tid; i < 12 * 128; i += NTHR) sWy[i] = ((const ull*)dWy)[i];
    for (int i = tid; i < D_; i += NTHR) {
        sbe[i] = pk(ebx[i], 0.f);
        sbd[i] = pk(dbx[i], 0.f);
    }
    if (tid < K_) sby[tid] = dby[tid];
    if (tid == 0) { mbar_init(mb_u32, 1); mbar_init(mb_u32 + 8, 1); }
    __syncthreads();

    // stage x_0 into buf0 aug rows (192 slots: tid, and tid+128 for tid<64)
    {
        const float2 a = *(const float2*)(x + ((size_t)rowbase + r1) * C_ + 2 * c1);
        sh0[(128 + c1) * RB + r1] = pk(a.x, a.y);
        if (tid < 64) {
            const float2 b = *(const float2*)(x + ((size_t)rowbase + r1) * C_ + 2 * (4 + c1));
            sh0[(132 + c1) * RB + r1] = pk(b.x, b.y);
        }
    }
    if (tid == 0) {   // prime chunks g=0 (buf0), g=1 (buf1), phase 0
        tma_issue(mb_u32,     sW_u32,           (const char*)g_Wp);
        tma_issue(mb_u32 + 8, sW_u32 + CHBYTES, (const char*)g_Wp + (size_t)CH * D_ * 8);
    }
    __syncthreads();

    ull acc[64];

    for (int t = 0; t < 2 * T_; ++t) {
        const bool dec = (t >= T_);
        ull* cur = (t & 1) ? sh1 : sh0;
        ull* nxt = (t & 1) ? sh0 : sh1;

        // prefetch next x slice into regs (encoder)
        ull xv1 = 0ull, xv2 = 0ull;
        if (!dec && (t + 1) < T_) {
            const float2 a = *(const float2*)(x + ((size_t)(t + 1) * N_ + rowbase + r1) * C_ + 2 * c1);
            xv1 = pk(a.x, a.y);
            if (tid < 64) {
                const float2 b = *(const float2*)(x + ((size_t)(t + 1) * N_ + rowbase + r1) * C_ + 2 * (4 + c1));
                xv2 = pk(b.x, b.y);
            }
        }

        // acc init = {bias, 0}
        {
            const ulonglong2* bp = (const ulonglong2*)((dec ? sbd : sbe) + d0);
            ulonglong2 b01 = bp[0], b23 = bp[1], b45 = bp[2], b67 = bp[3];
            ull bj[8] = {b01.x, b01.y, b23.x, b23.y, b45.x, b45.y, b67.x, b67.y};
            #pragma unroll
            for (int i = 0; i < 8; ++i)
                #pragma unroll
                for (int j = 0; j < 8; ++j) acc[i * 8 + j] = bj[j];
        }

        // ---- GEMM: 4 chunks of 34 kp; depth-1 LDS register pipeline ----
        #pragma unroll 1
        for (int c = 0; c < NCHK; ++c) {
            const int g   = t * NCHK + c;
            const int b   = g & 1;
            const unsigned par = (unsigned)((g >> 1) & 1);
            mbar_wait(mb_u32 + b * 8, par);

            const ulonglong2* wq = (const ulonglong2*)(smW + (size_t)b * CHW + d0);
            const ulonglong2* hq = (const ulonglong2*)(cur + (size_t)(c * CH) * RB + r0);

            // prime kp0 into A
            ulonglong2 wA0 = wq[0], wA1 = wq[1], wA2 = wq[2], wA3 = wq[3];
            ulonglong2 hA0 = hq[0], hA1 = hq[1], hA2 = hq[2], hA3 = hq[3];

            #pragma unroll 2
            for (int kk = 0; kk < CH; kk += 2) {
                // load kp kk+1 into B
                wq += 128; hq += 16;
                ulonglong2 wB0 = wq[0], wB1 = wq[1], wB2 = wq[2], wB3 = wq[3];
                ulonglong2 hB0 = hq[0], hB1 = hq[1], hB2 = hq[2], hB3 = hq[3];

                // compute kp kk (A)
                row8(acc + 0,  hA0.x, wA0, wA1, wA2, wA3);
                row8(acc + 8,  hA0.y, wA0, wA1, wA2, wA3);
                row8(acc + 16, hA1.x, wA0, wA1, wA2, wA3);
                row8(acc + 24, hA1.y, wA0, wA1, wA2, wA3);
                row8(acc + 32, hA2.x, wA0, wA1, wA2, wA3);
                row8(acc + 40, hA2.y, wA0, wA1, wA2, wA3);
                row8(acc + 48, hA3.x, wA0, wA1, wA2, wA3);
                row8(acc + 56, hA3.y, wA0, wA1, wA2, wA3);

                // load kp kk+2 into A (over-read at chunk end -> pad row / adjacent smem)
                wq += 128; hq += 16;
                wA0 = wq[0]; wA1 = wq[1]; wA2 = wq[2]; wA3 = wq[3];
                hA0 = hq[0]; hA1 = hq[1]; hA2 = hq[2]; hA3 = hq[3];

                // compute kp kk+1 (B)
                row8(acc + 0,  hB0.x, wB0, wB1, wB2, wB3);
                row8(acc + 8,  hB0.y, wB0, wB1, wB2, wB3);
                row8(acc + 16, hB1.x, wB0, wB1, wB2, wB3);
                row8(acc + 24, hB1.y, wB0, wB1, wB2, wB3);
                row8(acc + 32, hB2.x, wB0, wB1, wB2, wB3);
                row8(acc + 40, hB2.y, wB0, wB1, wB2, wB3);
                row8(acc + 48, hB3.x, wB0, wB1, wB2, wB3);
                row8(acc + 56, hB3.y, wB0, wB1, wB2, wB3);
            }
            __syncthreads();   // buffer b consumed by all threads

            if (tid == 0 && (g + 2) < GTOT) {
                const int g2 = g + 2;
                const int t2 = g2 >> 2, c2 = g2 & 3;
                const int ph = (t2 >= T_) ? 1 : 0;
                tma_issue(mb_u32 + b * 8, sW_u32 + b * CHBYTES,
                          (const char*)g_Wp + ((size_t)ph * KPAD + c2 * CH) * D_ * 8);
            }
        }

        // ---- epilogue: h = relu(lo+hi), store paired h into NXT ----
        #pragma unroll
        for (int j2 = 0; j2 < 4; ++j2) {
            float4* dst = (float4*)(nxt + (size_t)((d0 >> 1) + j2) * RB + r0);
            #pragma unroll
            for (int i2 = 0; i2 < 4; ++i2) {   // rows 2*i2, 2*i2+1
                float a0, b0, a1, b1, a2, b2, a3, b3;
                unpack2(acc[(2 * i2) * 8 + 2 * j2],         a0, b0);
                unpack2(acc[(2 * i2) * 8 + 2 * j2 + 1],     a1, b1);
                unpack2(acc[(2 * i2 + 1) * 8 + 2 * j2],     a2, b2);
                unpack2(acc[(2 * i2 + 1) * 8 + 2 * j2 + 1], a3, b3);
                dst[i2] = make_float4(fmaxf(a0 + b0, 0.f), fmaxf(a1 + b1, 0.f),
                                      fmaxf(a2 + b2, 0.f), fmaxf(a3 + b3, 0.f));
            }
        }
        if (!dec) {   // stage x_{t+1} or SOS (col 10 -> pair 5 = {1,0}) into NXT aug
            if (t + 1 < T_) {
                nxt[(128 + c1) * RB + r1] = xv1;
                if (tid < 64) nxt[(132 + c1) * RB + r1] = xv2;
            } else {
                nxt[(128 + c1) * RB + r1] = 0ull;
                if (tid < 64) nxt[(132 + c1) * RB + r1] = (c1 == 1) ? pk(1.f, 0.f) : 0ull;
            }
        }
        __syncthreads();   // publish new h (+aug)

        // ---- decoder: tiled y = h @ Wy^T + by (4 warps), argmax, feedback ----
        if (dec) {
            const int kg = lane & 3;          // k in {kg, kg+4, kg+8}
            const int mg = lane >> 2;         // m-chunk [16*mg, 16*mg+16)
            const int rw = warp * 8;          // 8 rows per warp
            const ull* w0 = sWy + kg * 128;
            const ull* w1 = sWy + (kg + 4) * 128;
            const ull* w2 = sWy + (kg + 8) * 128;
            ull a[24];                         // [row 8][k 3]
            #pragma unroll
            for (int q = 0; q < 24; ++q) a[q] = 0ull;
            const int mbase = mg * 16;
            #pragma unroll 4
            for (int mm = 0; mm < 16; ++mm) {
                const int m = mbase + mm;
                const ulonglong2* hp = (const ulonglong2*)(nxt + (size_t)m * RB + rw);
                ulonglong2 h01 = hp[0], h23 = hp[1], h45 = hp[2], h67 = hp[3];
                ull hr[8] = {h01.x, h01.y, h23.x, h23.y, h45.x, h45.y, h67.x, h67.y};
                ull wv0 = w0[m], wv1 = w1[m], wv2 = w2[m];
                #pragma unroll
                for (int i = 0; i < 8; ++i) {
                    ffma2(a[i * 3 + 0], hr[i], wv0);
                    ffma2(a[i * 3 + 1], hr[i], wv1);
                    ffma2(a[i * 3 + 2], hr[i], wv2);
                }
            }
            float v[24];
            #pragma unroll
            for (int q = 0; q < 24; ++q) {
                float lo, hi; unpack2(a[q], lo, hi);
                v[q] = lo + hi;
            }
            #pragma unroll
            for (int q = 0; q < 24; ++q) {
                v[q] += shflx(v[q], 4);
                v[q] += shflx(v[q], 8);
                v[q] += shflx(v[q], 16);
            }
            if (mg == 0) {
                #pragma unroll
                for (int i = 0; i < 8; ++i) {
                    yt[(rw + i) * 12 + kg]     = v[i * 3 + 0] + sby[kg];
                    yt[(rw + i) * 12 + kg + 4] = v[i * 3 + 1] + sby[kg + 4];
                    yt[(rw + i) * 12 + kg + 8] = v[i * 3 + 2] + sby[kg + 8];
                }
            }
            __syncthreads();   // yt complete
            if (tid < 32) {
                const float* yr = yt + tid * 12;
                float vv[12];
                #pragma unroll
                for (int q = 0; q < 3; ++q) {
                    float4 fv = *(const float4*)(yr + 4 * q);
                    vv[4 * q] = fv.x; vv[4 * q + 1] = fv.y;
                    vv[4 * q + 2] = fv.z; vv[4 * q + 3] = fv.w;
                }
                float best = vv[0]; int sel = 0;
                #pragma unroll
                for (int q = 1; q < 12; ++q)
                    if (vv[q] > best) { best = vv[q]; sel = q; }   // first-max wins
                float* og = out + ((size_t)(t - T_) * N_ + rowbase + tid) * K_;
                *(float4*)(og)     = make_float4(vv[0], vv[1], vv[2],  vv[3]);
                *(float4*)(og + 4) = make_float4(vv[4], vv[5], vv[6],  vv[7]);
                *(float4*)(og + 8) = make_float4(vv[8], vv[9], vv[10], vv[11]);
                // NXT aug: zero all 6 pair-cols for this row, set one-hot.
                // Visible to next step's chunk-3 reads via 3 intervening chunk barriers.
                const ull oh = (sel & 1) ? pk(0.f, 1.f) : pk(1.f, 0.f);
                #pragma unroll
                for (int cc = 0; cc < 6; ++cc)
                    nxt[(128 + cc) * RB + tid] = (cc == (sel >> 1)) ? oh : 0ull;
            }
            // no trailing barrier: warp0 joins chunk-0 barrier of next step
        }
    }
}

extern "C" void kernel_launch(void* const* d_in, const int* in_sizes, int n_in,
                              void* d_out, int out_size) {
    const float* x   = (const float*)d_in[0];
    const float* eWx = (const float*)d_in[1];
    const float* ebx = (const float*)d_in[2];
    const float* eWh = (const float*)d_in[3];
    const float* dWx = (const float*)d_in[6];
    const float* dbx = (const float*)d_in[7];
    const float* dWh = (const float*)d_in[8];
    const float* dWy = (const float*)d_in[9];
    const float* dby = (const float*)d_in[10];

    prep_kernel<<<2 * KPAD, D_>>>(eWh, eWx, dWh, dWx);

    cudaFuncSetAttribute(seq2seq_kernel,
                         cudaFuncAttributeMaxDynamicSharedMemorySize, SMEM_BYTES);
    seq2seq_kernel<<<NBLK, NTHR, SMEM_BYTES>>>(
        x, ebx, dbx, dWy, dby, (float*)d_out);
}